// round 14
// baseline (speedup 1.0000x reference)
#include <cuda_runtime.h>
#include <cuda_bf16.h>
#include <cuda_fp16.h>

// Problem constants
#define Bc 4
#define Sc 2048
#define Dc 1024
#define Hc 16
#define Mrows (Bc*Sc)   // 8192

#define SCALE_Q 0.18033688010819965f   // 0.125 * log2(e)

// ---------------------------------------------------------------------------
// Device scratch (u32 = packed pair of 16-bit values), all fp16 planes
// ---------------------------------------------------------------------------
__device__ unsigned g_Wqhi[1024*512], g_Wqlo[1024*512];
__device__ unsigned g_Wkhi[1024*512], g_Wklo[1024*512];
__device__ unsigned g_Wvhi[1024*512], g_Wvlo[1024*512];
__device__ unsigned g_Wohi[1024*512], g_Wolo[1024*512];
__device__ unsigned g_Xqhi[(size_t)Mrows*512], g_Xqlo[(size_t)Mrows*512];
__device__ unsigned g_Xkhi[(size_t)Mrows*512], g_Xklo[(size_t)Mrows*512];
__device__ unsigned g_Xvhi[(size_t)Mrows*512], g_Xvlo[(size_t)Mrows*512];
// Q head layout [B,H,S,32] fp16 split; K single fp16 plane
__device__ unsigned g_Qhi[(size_t)Mrows*512], g_Qlo[(size_t)Mrows*512];
__device__ unsigned g_Khi[(size_t)Mrows*512];
// V transposed head layout [B,H,64(hd),1024(key-pair)] fp16 split
__device__ unsigned g_Vthi[(size_t)Mrows*512], g_Vtlo[(size_t)Mrows*512];
// ctx [B,S,512] fp16 split
__device__ unsigned g_Chi[(size_t)Mrows*512], g_Clo[(size_t)Mrows*512];

// ---------------------------------------------------------------------------
// Helpers
// ---------------------------------------------------------------------------
__device__ __forceinline__ void split_pair_f16(float x0, float x1,
                                               unsigned& hi, unsigned& lo)
{
    __half2 h2 = __floats2half2_rn(x0, x1);
    float2 hf = __half22float2(h2);
    __half2 l2 = __floats2half2_rn(x0 - hf.x, x1 - hf.y);
    hi = *reinterpret_cast<unsigned*>(&h2);
    lo = *reinterpret_cast<unsigned*>(&l2);
}

// 2^a, 2^b as packed fp16 pair via one MUFU op
__device__ __forceinline__ unsigned ex2_f16x2(float a, float b)
{
    __half2 h = __floats2half2_rn(a, b);
    unsigned hu = *reinterpret_cast<unsigned*>(&h);
    unsigned r;
    asm("ex2.approx.f16x2 %0, %1;" : "=r"(r) : "r"(hu));
    return r;
}

__device__ __forceinline__ void mma16816f16(float c[4], const unsigned a[4],
                                            const unsigned b[2])
{
    asm volatile(
        "mma.sync.aligned.m16n8k16.row.col.f32.f16.f16.f32 "
        "{%0,%1,%2,%3}, {%4,%5,%6,%7}, {%8,%9}, {%0,%1,%2,%3};\n"
        : "+f"(c[0]), "+f"(c[1]), "+f"(c[2]), "+f"(c[3])
        : "r"(a[0]), "r"(a[1]), "r"(a[2]), "r"(a[3]),
          "r"(b[0]), "r"(b[1]));
}

__device__ __forceinline__ void ldsm4(unsigned r[4], const unsigned* p)
{
    unsigned a = (unsigned)__cvta_generic_to_shared(p);
    asm volatile("ldmatrix.sync.aligned.m8n8.x4.shared.b16 {%0,%1,%2,%3}, [%4];\n"
                 : "=r"(r[0]), "=r"(r[1]), "=r"(r[2]), "=r"(r[3]) : "r"(a));
}

__device__ __forceinline__ void cp16(void* smem, const void* g)
{
    unsigned sa = (unsigned)__cvta_generic_to_shared(smem);
    asm volatile("cp.async.cg.shared.global [%0], [%1], 16;\n"
                 :: "r"(sa), "l"(g) : "memory");
}

// ---------------------------------------------------------------------------
// Batched split converter (fp16 hi/lo)
// ---------------------------------------------------------------------------
__global__ __launch_bounds__(256)
void split4_kernel(const float4* __restrict__ i0, const float4* __restrict__ i1,
                   const float4* __restrict__ i2, const float4* __restrict__ i3,
                   uint2* __restrict__ h0, uint2* __restrict__ h1,
                   uint2* __restrict__ h2, uint2* __restrict__ h3,
                   uint2* __restrict__ l0, uint2* __restrict__ l1,
                   uint2* __restrict__ l2, uint2* __restrict__ l3)
{
    const float4* in; uint2 *hi, *lo;
    switch (blockIdx.y) {
        case 0:  in = i0; hi = h0; lo = l0; break;
        case 1:  in = i1; hi = h1; lo = l1; break;
        case 2:  in = i2; hi = h2; lo = l2; break;
        default: in = i3; hi = h3; lo = l3; break;
    }
    int i = blockIdx.x * 256 + threadIdx.x;
    float4 f = in[i];
    unsigned a0, b0, a1, b1;
    split_pair_f16(f.x, f.y, a0, b0);
    split_pair_f16(f.z, f.w, a1, b1);
    hi[i] = make_uint2(a0, a1);
    lo[i] = make_uint2(b0, b1);
}

// ---------------------------------------------------------------------------
// Shared GEMM mainloop: fp16 2-pass (X split hi/lo, W hi only), 3-stage
// cp.async pipeline, ldmatrix fragments, pass-major MMA order.
// ---------------------------------------------------------------------------
#define KPAD 20
#define HALF_U32 (128*KPAD)
#define STAGE_U32 (3*HALF_U32)
#define GEMM_SMEM (3*STAGE_U32*4)   // 92160 bytes

__device__ __forceinline__ void gemm_mainloop(
    const unsigned* __restrict__ Xhi, const unsigned* __restrict__ Xlo,
    const unsigned* __restrict__ Whi,
    int m0, int n0, unsigned* sg, float c[4][4][4])
{
    const int t    = threadIdx.x;
    const int lane = t & 31;
    const int wid  = t >> 5;
    const int wm   = wid >> 2;
    const int wn   = wid & 3;

    const int agrp  = lane >> 3;
    const int l7    = lane & 7;
    const int a_row = l7 + ((agrp & 1) << 3);
    const int a_col = (agrp >> 1) << 2;
    const int b_row = l7 + ((agrp >> 1) << 3);
    const int b_col = (agrp & 1) << 2;

    auto issue = [&](int stage, int kt) {
        unsigned* base = sg + stage * STAGE_U32;
#pragma unroll
        for (int j = 0; j < 6; ++j) {
            int id   = t + j * 256;
            int half = id >> 9;
            int rem  = id & 511;
            int row  = rem >> 2;
            int c4   = (rem & 3) << 2;
            const unsigned* src;
            if      (half == 0) src = Xhi + (size_t)(m0 + row) * 512 + kt * 16 + c4;
            else if (half == 1) src = Xlo + (size_t)(m0 + row) * 512 + kt * 16 + c4;
            else                src = Whi + (size_t)(n0 + row) * 512 + kt * 16 + c4;
            cp16(base + half * HALF_U32 + row * KPAD + c4, src);
        }
        asm volatile("cp.async.commit_group;\n" ::: "memory");
    };

    issue(0, 0);
    issue(1, 1);

    const int NT = 32;
    for (int kt = 0; kt < NT; ++kt) {
        if (kt + 2 < NT) {
            issue((kt + 2) % 3, kt + 2);
            asm volatile("cp.async.wait_group 2;\n" ::: "memory");
        } else if (kt + 1 < NT) {
            asm volatile("cp.async.wait_group 1;\n" ::: "memory");
        } else {
            asm volatile("cp.async.wait_group 0;\n" ::: "memory");
        }
        __syncthreads();

        const unsigned* Ah = sg + (kt % 3) * STAGE_U32;
        const unsigned* Al = Ah + HALF_U32;
        const unsigned* Bh = Ah + 2 * HALF_U32;

#pragma unroll
        for (int ks = 0; ks < 2; ++ks) {
            const int pb = ks * 8;
            unsigned ahi[4][4], alo[4][4], bhi[2][4];
#pragma unroll
            for (int mf = 0; mf < 4; ++mf) {
                const int r = (wm * 64 + mf * 16 + a_row) * KPAD + pb + a_col;
                ldsm4(ahi[mf], Ah + r);
                ldsm4(alo[mf], Al + r);
            }
#pragma unroll
            for (int np = 0; np < 2; ++np) {
                const int r = (wn * 32 + np * 16 + b_row) * KPAD + pb + b_col;
                ldsm4(bhi[np], Bh + r);
            }
#pragma unroll
            for (int mf = 0; mf < 4; ++mf)
#pragma unroll
                for (int nf = 0; nf < 4; ++nf)
                    mma16816f16(c[mf][nf], ahi[mf], &bhi[nf >> 1][(nf & 1) * 2]);
#pragma unroll
            for (int mf = 0; mf < 4; ++mf)
#pragma unroll
                for (int nf = 0; nf < 4; ++nf)
                    mma16816f16(c[mf][nf], alo[mf], &bhi[nf >> 1][(nf & 1) * 2]);
        }
        __syncthreads();
    }
}

// ---------------------------------------------------------------------------
// Merged Q/K/V projection GEMM: z=0 Q (fp16 split out, scaled),
// z=1 K (single fp16 out), z=2 V (transposed fp16 split out).
// ---------------------------------------------------------------------------
__global__ __launch_bounds__(256, 2)
void gemm_qkv_kernel(const unsigned* __restrict__ xqh, const unsigned* __restrict__ xql,
                     const unsigned* __restrict__ xkh, const unsigned* __restrict__ xkl,
                     const unsigned* __restrict__ xvh, const unsigned* __restrict__ xvl,
                     const unsigned* __restrict__ wqh,
                     const unsigned* __restrict__ wkh,
                     const unsigned* __restrict__ wvh,
                     const float* __restrict__ bq, const float* __restrict__ bk,
                     const float* __restrict__ bv,
                     unsigned* __restrict__ qh, unsigned* __restrict__ ql,
                     unsigned* __restrict__ kh,
                     unsigned* __restrict__ vth, unsigned* __restrict__ vtl)
{
    extern __shared__ unsigned sg[];

    const int z = blockIdx.z;
    const unsigned *Xhi, *Xlo, *Whi;
    const float* bias;
    float scale;
    if (z == 0) { Xhi = xqh; Xlo = xql; Whi = wqh; bias = bq; scale = SCALE_Q; }
    else if (z == 1) { Xhi = xkh; Xlo = xkl; Whi = wkh; bias = bk; scale = 1.0f; }
    else { Xhi = xvh; Xlo = xvl; Whi = wvh; bias = bv; scale = 1.0f; }

    const int t    = threadIdx.x;
    const int lane = t & 31;
    const int wid  = t >> 5;
    const int wm   = wid >> 2;
    const int wn   = wid & 3;
    const int g    = lane >> 2;
    const int tig  = lane & 3;
    const int m0 = blockIdx.y * 128;
    const int n0 = blockIdx.x * 128;

    float c[4][4][4];
#pragma unroll
    for (int i = 0; i < 4; ++i)
#pragma unroll
        for (int j = 0; j < 4; ++j)
#pragma unroll
            for (int e = 0; e < 4; ++e) c[i][j][e] = 0.0f;

    gemm_mainloop(Xhi, Xlo, Whi, m0, n0, sg, c);

#pragma unroll
    for (int mf = 0; mf < 4; ++mf) {
#pragma unroll
        for (int nf = 0; nf < 4; ++nf) {
            int m = m0 + wm * 64 + mf * 16 + g;
            int n = n0 + wn * 32 + nf * 8 + tig * 2;
            float v0 = (c[mf][nf][0] + bias[n]) * scale;
            float v1 = (c[mf][nf][1] + bias[n + 1]) * scale;
            float v2 = (c[mf][nf][2] + bias[n]) * scale;
            float v3 = (c[mf][nf][3] + bias[n + 1]) * scale;
            int b = m >> 11, s = m & 2047;
            int h = n >> 6, hd = n & 63;
            if (z == 0) {
                unsigned hh, ll;
                split_pair_f16(v0, v1, hh, ll);
                size_t p0 = (((size_t)(b * Hc + h)) * Sc + s) * 32 + (hd >> 1);
                qh[p0] = hh; ql[p0] = ll;
                split_pair_f16(v2, v3, hh, ll);
                size_t p1 = (((size_t)(b * Hc + h)) * Sc + (s + 8)) * 32 + (hd >> 1);
                qh[p1] = hh; ql[p1] = ll;
            } else if (z == 1) {
                __half2 h01 = __floats2half2_rn(v0, v1);
                __half2 h23 = __floats2half2_rn(v2, v3);
                size_t p0 = (((size_t)(b * Hc + h)) * Sc + s) * 32 + (hd >> 1);
                size_t p1 = (((size_t)(b * Hc + h)) * Sc + (s + 8)) * 32 + (hd >> 1);
                kh[p0] = *reinterpret_cast<unsigned*>(&h01);
                kh[p1] = *reinterpret_cast<unsigned*>(&h23);
            } else {
                float p0 = __shfl_xor_sync(0xffffffffu, v0, 4);
                float p1 = __shfl_xor_sync(0xffffffffu, v1, 4);
                float p2 = __shfl_xor_sync(0xffffffffu, v2, 4);
                float p3 = __shfl_xor_sync(0xffffffffu, v3, 4);
                if (!(g & 1)) {
                    size_t rb = ((size_t)(b * Hc + h)) * 64;
                    int kp = s >> 1;
                    unsigned hh, ll;
                    split_pair_f16(v0, p0, hh, ll);
                    vth[(rb + hd) * 1024 + kp] = hh;     vtl[(rb + hd) * 1024 + kp] = ll;
                    split_pair_f16(v1, p1, hh, ll);
                    vth[(rb + hd + 1) * 1024 + kp] = hh; vtl[(rb + hd + 1) * 1024 + kp] = ll;
                    split_pair_f16(v2, p2, hh, ll);
                    vth[(rb + hd) * 1024 + kp + 4] = hh;     vtl[(rb + hd) * 1024 + kp + 4] = ll;
                    split_pair_f16(v3, p3, hh, ll);
                    vth[(rb + hd + 1) * 1024 + kp + 4] = hh; vtl[(rb + hd + 1) * 1024 + kp + 4] = ll;
                }
            }
        }
    }
}

// ---------------------------------------------------------------------------
// Output GEMM: ctx(fp16 split) @ Wo(hi)^T + bo -> fp32 out
// ---------------------------------------------------------------------------
__global__ __launch_bounds__(256, 2)
void gemm_out_kernel(const unsigned* __restrict__ Xhi, const unsigned* __restrict__ Xlo,
                     const unsigned* __restrict__ Whi,
                     const float* __restrict__ bias, float* __restrict__ outf)
{
    extern __shared__ unsigned sg[];

    const int t    = threadIdx.x;
    const int lane = t & 31;
    const int wid  = t >> 5;
    const int wm   = wid >> 2;
    const int wn   = wid & 3;
    const int g    = lane >> 2;
    const int tig  = lane & 3;
    const int m0 = blockIdx.y * 128;
    const int n0 = blockIdx.x * 128;

    float c[4][4][4];
#pragma unroll
    for (int i = 0; i < 4; ++i)
#pragma unroll
        for (int j = 0; j < 4; ++j)
#pragma unroll
            for (int e = 0; e < 4; ++e) c[i][j][e] = 0.0f;

    gemm_mainloop(Xhi, Xlo, Whi, m0, n0, sg, c);

#pragma unroll
    for (int mf = 0; mf < 4; ++mf) {
#pragma unroll
        for (int nf = 0; nf < 4; ++nf) {
            int m = m0 + wm * 64 + mf * 16 + g;
            int n = n0 + wn * 32 + nf * 8 + tig * 2;
            outf[(size_t)m * Dc + n]           = c[mf][nf][0] + bias[n];
            outf[(size_t)m * Dc + n + 1]       = c[mf][nf][1] + bias[n + 1];
            outf[(size_t)(m + 8) * Dc + n]     = c[mf][nf][2] + bias[n];
            outf[(size_t)(m + 8) * Dc + n + 1] = c[mf][nf][3] + bias[n + 1];
        }
    }
}

// ---------------------------------------------------------------------------
// Flash attention: fp16 2-pass QK, ex2.approx.f16x2 softmax, fp16 P +
// fp16-split V 2-pass PV, cp.async double-buffered (Kh,Vh,Vl per stage).
// ---------------------------------------------------------------------------
#define AT_STAGE_U32 (3*64*36)
#define ATTN4_SMEM_U32 (2*128*36 + 2*AT_STAGE_U32)
#define ATTN4_SMEM_BYTES (ATTN4_SMEM_U32 * 4)   // 92160

__global__ __launch_bounds__(256, 2)
void attn_mma_kernel(const unsigned* __restrict__ Qhg, const unsigned* __restrict__ Qlg,
                     const unsigned* __restrict__ Khg,
                     const unsigned* __restrict__ Vthg, const unsigned* __restrict__ Vtlg,
                     unsigned* __restrict__ Chi, unsigned* __restrict__ Clo)
{
    extern __shared__ unsigned smu[];
    unsigned* Qsh = smu;                    // [128][36]
    unsigned* Qsl = Qsh + 128 * 36;
    unsigned* stages = Qsl + 128 * 36;

    const int bh = blockIdx.y;
    const int qt = (int)(gridDim.x - 1 - blockIdx.x);
    const int q0 = qt * 128;
    const int t    = threadIdx.x;
    const int lane = t & 31;
    const int w    = t >> 5;
    const int g    = lane >> 2;
    const int tig  = lane & 3;

    const int agrp  = lane >> 3;
    const int l7    = lane & 7;
    const int a_row = l7 + ((agrp & 1) << 3);
    const int a_col = (agrp >> 1) << 2;
    const int b_row = l7 + ((agrp >> 1) << 3);
    const int b_col = (agrp & 1) << 2;

    const unsigned* Qbh = Qhg + (size_t)bh * Sc * 32;
    const unsigned* Qbl = Qlg + (size_t)bh * Sc * 32;
    const unsigned* Kbh = Khg + (size_t)bh * Sc * 32;
    const unsigned* Vbh = Vthg + (size_t)bh * 64 * 1024;
    const unsigned* Vbl = Vtlg + (size_t)bh * 64 * 1024;

#pragma unroll
    for (int j = 0; j < 4; ++j) {
        int id = t + j * 256;
        int r = id >> 3, c4 = (id & 7) << 2;
        cp16(&Qsh[r * 36 + c4], &Qbh[(size_t)(q0 + r) * 32 + c4]);
        cp16(&Qsl[r * 36 + c4], &Qbl[(size_t)(q0 + r) * 32 + c4]);
    }
    asm volatile("cp.async.commit_group;\n" ::: "memory");

    auto stage_fn = [&](int st, int kt) {
        unsigned* Kh = stages + st * AT_STAGE_U32;
        unsigned* Vh = Kh + 64 * 36;
        unsigned* Vl = Vh + 64 * 36;
        const int k0 = kt * 64, kp0 = kt * 32;
#pragma unroll
        for (int j = 0; j < 2; ++j) {
            int id = t + j * 256;
            int r = id >> 3, c4 = (id & 7) << 2;
            cp16(Kh + r * 36 + c4, Kbh + (size_t)(k0 + r) * 32 + c4);
            cp16(Vh + r * 36 + c4, Vbh + (size_t)r * 1024 + kp0 + c4);
            cp16(Vl + r * 36 + c4, Vbl + (size_t)r * 1024 + kp0 + c4);
        }
        asm volatile("cp.async.commit_group;\n" ::: "memory");
    };

    float m_i[2] = {-1e30f, -1e30f};
    float l_i[2] = {0.0f, 0.0f};
    float o[8][4];
#pragma unroll
    for (int f = 0; f < 8; ++f)
#pragma unroll
        for (int e = 0; e < 4; ++e) o[f][e] = 0.0f;

    const int row0 = q0 + w * 16 + g;
    const int nkt = 2 * qt + 2;

    stage_fn(0, 0);

    for (int kt = 0; kt < nkt; ++kt) {
        const int k0 = kt * 64;
        __syncthreads();
        if (kt + 1 < nkt) {
            stage_fn((kt + 1) & 1, kt + 1);
            asm volatile("cp.async.wait_group 1;\n" ::: "memory");
        } else {
            asm volatile("cp.async.wait_group 0;\n" ::: "memory");
        }
        __syncthreads();

        if (q0 + w * 16 + 15 < k0) continue;

        const unsigned* Ksh = stages + (kt & 1) * AT_STAGE_U32;
        const unsigned* Vsh = Ksh + 64 * 36;
        const unsigned* Vsl = Vsh + 64 * 36;

        // ---- S = Q K^T (fp16 2-pass) ----
        float s[8][4];
#pragma unroll
        for (int nf = 0; nf < 8; ++nf)
#pragma unroll
            for (int e = 0; e < 4; ++e) s[nf][e] = 0.0f;

#pragma unroll
        for (int ks = 0; ks < 4; ++ks) {
            unsigned aqh[4], aql[4];
            const int qoff = (w * 16 + a_row) * 36 + 8 * ks + a_col;
            ldsm4(aqh, Qsh + qoff);
            ldsm4(aql, Qsl + qoff);
            unsigned khi[4][4];
#pragma unroll
            for (int np = 0; np < 4; ++np) {
                const int koff = (np * 16 + b_row) * 36 + 8 * ks + b_col;
                ldsm4(khi[np], Ksh + koff);
            }
#pragma unroll
            for (int nf = 0; nf < 8; ++nf)
                mma16816f16(s[nf], aqh, &khi[nf >> 1][(nf & 1) * 2]);
#pragma unroll
            for (int nf = 0; nf < 8; ++nf)
                mma16816f16(s[nf], aql, &khi[nf >> 1][(nf & 1) * 2]);
        }

        // ---- causal mask ----
        if (k0 + 63 > q0 + w * 16) {
#pragma unroll
            for (int nf = 0; nf < 8; ++nf) {
                int key = k0 + 8 * nf + 2 * tig;
                if (key     > row0)     s[nf][0] = -1e30f;
                if (key + 1 > row0)     s[nf][1] = -1e30f;
                if (key     > row0 + 8) s[nf][2] = -1e30f;
                if (key + 1 > row0 + 8) s[nf][3] = -1e30f;
            }
        }

        // ---- online softmax (base-2 domain, fp16x2 ex2) ----
        float mx0 = -1e30f, mx1 = -1e30f;
#pragma unroll
        for (int nf = 0; nf < 8; ++nf) {
            mx0 = fmaxf(mx0, fmaxf(s[nf][0], s[nf][1]));
            mx1 = fmaxf(mx1, fmaxf(s[nf][2], s[nf][3]));
        }
        mx0 = fmaxf(mx0, __shfl_xor_sync(0xffffffffu, mx0, 1));
        mx0 = fmaxf(mx0, __shfl_xor_sync(0xffffffffu, mx0, 2));
        mx1 = fmaxf(mx1, __shfl_xor_sync(0xffffffffu, mx1, 1));
        mx1 = fmaxf(mx1, __shfl_xor_sync(0xffffffffu, mx1, 2));

        float mn0 = fmaxf(m_i[0], mx0);
        float mn1 = fmaxf(m_i[1], mx1);
        float cs0 = exp2f(m_i[0] - mn0);
        float cs1 = exp2f(m_i[1] - mn1);
        m_i[0] = mn0; m_i[1] = mn1;

        // P directly in fp16 via ex2.approx.f16x2 (P used in PV == P summed in l)
        unsigned pf[8][2];
        float sum0 = 0.0f, sum1 = 0.0f;
#pragma unroll
        for (int nf = 0; nf < 8; ++nf) {
            pf[nf][0] = ex2_f16x2(s[nf][0] - mn0, s[nf][1] - mn0);
            pf[nf][1] = ex2_f16x2(s[nf][2] - mn1, s[nf][3] - mn1);
            float2 f01 = __half22float2(*reinterpret_cast<__half2*>(&pf[nf][0]));
            float2 f23 = __half22float2(*reinterpret_cast<__half2*>(&pf[nf][1]));
            sum0 += f01.x + f01.y;
            sum1 += f23.x + f23.y;
        }
        sum0 += __shfl_xor_sync(0xffffffffu, sum0, 1);
        sum0 += __shfl_xor_sync(0xffffffffu, sum0, 2);
        sum1 += __shfl_xor_sync(0xffffffffu, sum1, 1);
        sum1 += __shfl_xor_sync(0xffffffffu, sum1, 2);
        l_i[0] = l_i[0] * cs0 + sum0;
        l_i[1] = l_i[1] * cs1 + sum1;

#pragma unroll
        for (int f = 0; f < 8; ++f) {
            o[f][0] *= cs0; o[f][1] *= cs0;
            o[f][2] *= cs1; o[f][3] *= cs1;
        }

        // ---- O += P V (fp16, 2-pass) ----
#pragma unroll
        for (int ks = 0; ks < 4; ++ks) {
            unsigned pa[4] = { pf[2 * ks][0], pf[2 * ks][1],
                               pf[2 * ks + 1][0], pf[2 * ks + 1][1] };
            unsigned vhi[4][4], vlo[4][4];
#pragma unroll
            for (int np = 0; np < 4; ++np) {
                const int voff = (np * 16 + b_row) * 36 + 8 * ks + b_col;
                ldsm4(vhi[np], Vsh + voff);
                ldsm4(vlo[np], Vsl + voff);
            }
#pragma unroll
            for (int nf = 0; nf < 8; ++nf)
                mma16816f16(o[nf], pa, &vhi[nf >> 1][(nf & 1) * 2]);
#pragma unroll
            for (int nf = 0; nf < 8; ++nf)
                mma16816f16(o[nf], pa, &vlo[nf >> 1][(nf & 1) * 2]);
        }
    }

    // ---- epilogue: normalize, fp16 split, write ctx ----
    const float inv0 = 1.0f / l_i[0];
    const float inv1 = 1.0f / l_i[1];
    const int b = bh >> 4;
    const int h = bh & 15;
#pragma unroll
    for (int nf = 0; nf < 8; ++nf) {
        int col = 8 * nf + 2 * tig;
        unsigned hh, ll;
        split_pair_f16(o[nf][0] * inv0, o[nf][1] * inv0, hh, ll);
        size_t p0 = ((size_t)b * Sc + row0) * 512 + h * 32 + (col >> 1);
        Chi[p0] = hh; Clo[p0] = ll;
        split_pair_f16(o[nf][2] * inv1, o[nf][3] * inv1, hh, ll);
        size_t p1 = ((size_t)b * Sc + row0 + 8) * 512 + h * 32 + (col >> 1);
        Chi[p1] = hh; Clo[p1] = ll;
    }
}

// ---------------------------------------------------------------------------
// Launch
// ---------------------------------------------------------------------------
#define SYMADDR(p, s) do { void* _tmp; cudaGetSymbolAddress(&_tmp, s); p = (unsigned*)_tmp; } while (0)

extern "C" void kernel_launch(void* const* d_in, const int* in_sizes, int n_in,
                              void* d_out, int out_size)
{
    const float* q  = (const float*)d_in[0];
    const float* k  = (const float*)d_in[1];
    const float* v  = (const float*)d_in[2];
    const float* Wq = (const float*)d_in[4];
    const float* bq = (const float*)d_in[5];
    const float* Wk = (const float*)d_in[6];
    const float* bk = (const float*)d_in[7];
    const float* Wv = (const float*)d_in[8];
    const float* bv = (const float*)d_in[9];
    const float* Wo = (const float*)d_in[10];
    const float* bo = (const float*)d_in[11];
    float* out = (float*)d_out;

    unsigned *wqh,*wql,*wkh,*wkl,*wvh,*wvl,*woh,*wol;
    unsigned *xqh,*xql,*xkh,*xkl,*xvh,*xvl;
    unsigned *qh,*ql,*kh,*vth,*vtl,*ch,*cl;
    SYMADDR(wqh, g_Wqhi); SYMADDR(wql, g_Wqlo);
    SYMADDR(wkh, g_Wkhi); SYMADDR(wkl, g_Wklo);
    SYMADDR(wvh, g_Wvhi); SYMADDR(wvl, g_Wvlo);
    SYMADDR(woh, g_Wohi); SYMADDR(wol, g_Wolo);
    SYMADDR(xqh, g_Xqhi); SYMADDR(xql, g_Xqlo);
    SYMADDR(xkh, g_Xkhi); SYMADDR(xkl, g_Xklo);
    SYMADDR(xvh, g_Xvhi); SYMADDR(xvl, g_Xvlo);
    SYMADDR(qh, g_Qhi);   SYMADDR(ql, g_Qlo);
    SYMADDR(kh, g_Khi);
    SYMADDR(vth, g_Vthi); SYMADDR(vtl, g_Vtlo);
    SYMADDR(ch, g_Chi);   SYMADDR(cl, g_Clo);

    cudaFuncSetAttribute(gemm_qkv_kernel, cudaFuncAttributeMaxDynamicSharedMemorySize, GEMM_SMEM);
    cudaFuncSetAttribute(gemm_out_kernel, cudaFuncAttributeMaxDynamicSharedMemorySize, GEMM_SMEM);
    cudaFuncSetAttribute(attn_mma_kernel, cudaFuncAttributeMaxDynamicSharedMemorySize, ATTN4_SMEM_BYTES);

    split4_kernel<<<dim3(1024, 4), 256>>>(
        (const float4*)Wq, (const float4*)Wk, (const float4*)Wv, (const float4*)Wo,
        (uint2*)wqh, (uint2*)wkh, (uint2*)wvh, (uint2*)woh,
        (uint2*)wql, (uint2*)wkl, (uint2*)wvl, (uint2*)wol);
    split4_kernel<<<dim3(8192, 3), 256>>>(
        (const float4*)q, (const float4*)k, (const float4*)v, (const float4*)v,
        (uint2*)xqh, (uint2*)xkh, (uint2*)xvh, (uint2*)xvh,
        (uint2*)xql, (uint2*)xkl, (uint2*)xvl, (uint2*)xvl);

    dim3 gg3(Dc / 128, Mrows / 128, 3);   // (8, 64, 3)
    gemm_qkv_kernel<<<gg3, 256, GEMM_SMEM>>>(
        xqh, xql, xkh, xkl, xvh, xvl,
        wqh, wkh, wvh,
        bq, bk, bv,
        qh, ql, kh, vth, vtl);

    dim3 ga(Sc / 128, Bc * Hc);           // (16, 64)
    attn_mma_kernel<<<ga, 256, ATTN4_SMEM_BYTES>>>(qh, ql, kh, vth, vtl, ch, cl);

    dim3 gg(Dc / 128, Mrows / 128);       // (8, 64)
    gemm_out_kernel<<<gg, 256, GEMM_SMEM>>>(ch, cl, woh, bo, out);
}

// round 15
// speedup vs baseline: 1.3301x; 1.3301x over previous
#include <cuda_runtime.h>
#include <cuda_bf16.h>
#include <cuda_fp16.h>

// Problem constants
#define Bc 4
#define Sc 2048
#define Dc 1024
#define Hc 16
#define Mrows (Bc*Sc)   // 8192

#define SCALE_Q 0.18033688010819965f   // 0.125 * log2(e)

// ---------------------------------------------------------------------------
// Device scratch (u32 = packed pair of fp16)
// ---------------------------------------------------------------------------
__device__ unsigned g_Wqhi[1024*512];
__device__ unsigned g_Wkhi[1024*512];
__device__ unsigned g_Wvhi[1024*512];
__device__ unsigned g_Wohi[1024*512];
__device__ unsigned g_Xqhi[(size_t)Mrows*512], g_Xqlo[(size_t)Mrows*512];
__device__ unsigned g_Xkhi[(size_t)Mrows*512];
__device__ unsigned g_Xvhi[(size_t)Mrows*512];
// Q head layout [B,H,S,32] fp16 split; K single fp16 plane
__device__ unsigned g_Qhi[(size_t)Mrows*512], g_Qlo[(size_t)Mrows*512];
__device__ unsigned g_Khi[(size_t)Mrows*512];
// V transposed head layout [B,H,64(hd),1024(key-pair)] single fp16
__device__ unsigned g_Vthi[(size_t)Mrows*512];
// ctx [B,S,512] single fp16
__device__ unsigned g_Chi[(size_t)Mrows*512];

// ---------------------------------------------------------------------------
// Helpers
// ---------------------------------------------------------------------------
__device__ __forceinline__ void split_pair_f16(float x0, float x1,
                                               unsigned& hi, unsigned& lo)
{
    __half2 h2 = __floats2half2_rn(x0, x1);
    float2 hf = __half22float2(h2);
    __half2 l2 = __floats2half2_rn(x0 - hf.x, x1 - hf.y);
    hi = *reinterpret_cast<unsigned*>(&h2);
    lo = *reinterpret_cast<unsigned*>(&l2);
}

__device__ __forceinline__ unsigned pack_f16(float x0, float x1)
{
    __half2 h2 = __floats2half2_rn(x0, x1);
    return *reinterpret_cast<unsigned*>(&h2);
}

__device__ __forceinline__ void mma16816f16(float c[4], const unsigned a[4],
                                            const unsigned b[2])
{
    asm volatile(
        "mma.sync.aligned.m16n8k16.row.col.f32.f16.f16.f32 "
        "{%0,%1,%2,%3}, {%4,%5,%6,%7}, {%8,%9}, {%0,%1,%2,%3};\n"
        : "+f"(c[0]), "+f"(c[1]), "+f"(c[2]), "+f"(c[3])
        : "r"(a[0]), "r"(a[1]), "r"(a[2]), "r"(a[3]),
          "r"(b[0]), "r"(b[1]));
}

__device__ __forceinline__ void ldsm4(unsigned r[4], const unsigned* p)
{
    unsigned a = (unsigned)__cvta_generic_to_shared(p);
    asm volatile("ldmatrix.sync.aligned.m8n8.x4.shared.b16 {%0,%1,%2,%3}, [%4];\n"
                 : "=r"(r[0]), "=r"(r[1]), "=r"(r[2]), "=r"(r[3]) : "r"(a));
}

__device__ __forceinline__ void cp16(void* smem, const void* g)
{
    unsigned sa = (unsigned)__cvta_generic_to_shared(smem);
    asm volatile("cp.async.cg.shared.global [%0], [%1], 16;\n"
                 :: "r"(sa), "l"(g) : "memory");
}

// ---------------------------------------------------------------------------
// Split converters
// ---------------------------------------------------------------------------
// Full hi/lo split (only q input needs lo)
__global__ __launch_bounds__(256)
void split_hl_kernel(const float4* __restrict__ in,
                     uint2* __restrict__ hi, uint2* __restrict__ lo)
{
    int i = blockIdx.x * 256 + threadIdx.x;
    float4 f = in[i];
    unsigned a0, b0, a1, b1;
    split_pair_f16(f.x, f.y, a0, b0);
    split_pair_f16(f.z, f.w, a1, b1);
    hi[i] = make_uint2(a0, a1);
    lo[i] = make_uint2(b0, b1);
}

// hi-only converter, batched over up to 6 matrices
__global__ __launch_bounds__(256)
void split_hi6_kernel(const float4* __restrict__ i0, const float4* __restrict__ i1,
                      const float4* __restrict__ i2, const float4* __restrict__ i3,
                      const float4* __restrict__ i4, const float4* __restrict__ i5,
                      uint2* __restrict__ o0, uint2* __restrict__ o1,
                      uint2* __restrict__ o2, uint2* __restrict__ o3,
                      uint2* __restrict__ o4, uint2* __restrict__ o5,
                      int n_small)   // matrices with index >= n_small are 8x larger
{
    const float4* in; uint2* out;
    switch (blockIdx.y) {
        case 0:  in = i0; out = o0; break;
        case 1:  in = i1; out = o1; break;
        case 2:  in = i2; out = o2; break;
        case 3:  in = i3; out = o3; break;
        case 4:  in = i4; out = o4; break;
        default: in = i5; out = o5; break;
    }
    int nblk = ((int)blockIdx.y < n_small) ? 1024 : 8192;
    if (blockIdx.x >= (unsigned)nblk) return;
    int i = blockIdx.x * 256 + threadIdx.x;
    float4 f = in[i];
    out[i] = make_uint2(pack_f16(f.x, f.y), pack_f16(f.z, f.w));
}

// ---------------------------------------------------------------------------
// Shared GEMM mainloop, templated on pass count.
// TWO=true:  X split hi/lo (2 passes vs W-hi). TWO=false: X hi only (1 pass).
// 2-stage cp.async pipeline, ldmatrix fragments, pass-major MMA order.
// ---------------------------------------------------------------------------
#define KPAD 20
#define HALF_U32 (128*KPAD)
#define STAGE_U32 (3*HALF_U32)
#define GEMM_SMEM (2*STAGE_U32*4)   // 61440 bytes

template <bool TWO>
__device__ __forceinline__ void gemm_mainloop(
    const unsigned* __restrict__ Xhi, const unsigned* __restrict__ Xlo,
    const unsigned* __restrict__ Whi,
    int m0, int n0, unsigned* sg, float c[4][4][4])
{
    const int t    = threadIdx.x;
    const int lane = t & 31;
    const int wid  = t >> 5;
    const int wm   = wid >> 2;
    const int wn   = wid & 3;

    const int agrp  = lane >> 3;
    const int l7    = lane & 7;
    const int a_row = l7 + ((agrp & 1) << 3);
    const int a_col = (agrp >> 1) << 2;
    const int b_row = l7 + ((agrp >> 1) << 3);
    const int b_col = (agrp & 1) << 2;

    auto issue = [&](int stage, int kt) {
        unsigned* base = sg + stage * STAGE_U32;
        const int NJ = TWO ? 6 : 4;
#pragma unroll
        for (int j = 0; j < NJ; ++j) {
            int id   = t + j * 256;
            int half = id >> 9;              // 0..NJ/2-1
            int rem  = id & 511;
            int row  = rem >> 2;
            int c4   = (rem & 3) << 2;
            const unsigned* src;
            unsigned soff;
            if (half == 0) { src = Xhi + (size_t)(m0 + row) * 512 + kt * 16 + c4; soff = 0; }
            else if (TWO && half == 1) { src = Xlo + (size_t)(m0 + row) * 512 + kt * 16 + c4; soff = HALF_U32; }
            else { src = Whi + (size_t)(n0 + row) * 512 + kt * 16 + c4; soff = 2 * HALF_U32; }
            cp16(base + soff + row * KPAD + c4, src);
        }
        asm volatile("cp.async.commit_group;\n" ::: "memory");
    };

    issue(0, 0);

    const int NT = 32;
    for (int kt = 0; kt < NT; ++kt) {
        if (kt + 1 < NT) {
            issue((kt + 1) & 1, kt + 1);
            asm volatile("cp.async.wait_group 1;\n" ::: "memory");
        } else {
            asm volatile("cp.async.wait_group 0;\n" ::: "memory");
        }
        __syncthreads();

        const unsigned* Ah = sg + (kt & 1) * STAGE_U32;
        const unsigned* Al = Ah + HALF_U32;
        const unsigned* Bh = Ah + 2 * HALF_U32;

#pragma unroll
        for (int ks = 0; ks < 2; ++ks) {
            const int pb = ks * 8;
            unsigned ahi[4][4], alo[4][4], bhi[2][4];
#pragma unroll
            for (int mf = 0; mf < 4; ++mf) {
                const int r = (wm * 64 + mf * 16 + a_row) * KPAD + pb + a_col;
                ldsm4(ahi[mf], Ah + r);
                if (TWO) ldsm4(alo[mf], Al + r);
            }
#pragma unroll
            for (int np = 0; np < 2; ++np) {
                const int r = (wn * 32 + np * 16 + b_row) * KPAD + pb + b_col;
                ldsm4(bhi[np], Bh + r);
            }
#pragma unroll
            for (int mf = 0; mf < 4; ++mf)
#pragma unroll
                for (int nf = 0; nf < 4; ++nf)
                    mma16816f16(c[mf][nf], ahi[mf], &bhi[nf >> 1][(nf & 1) * 2]);
            if (TWO) {
#pragma unroll
                for (int mf = 0; mf < 4; ++mf)
#pragma unroll
                    for (int nf = 0; nf < 4; ++nf)
                        mma16816f16(c[mf][nf], alo[mf], &bhi[nf >> 1][(nf & 1) * 2]);
            }
        }
        __syncthreads();
    }
}

// ---------------------------------------------------------------------------
// Merged Q/K/V projection GEMM: z=0 Q (2-pass, fp16 split out, scaled),
// z=1 K (1-pass, single fp16 out), z=2 V (1-pass, transposed single fp16 out).
// ---------------------------------------------------------------------------
__global__ __launch_bounds__(256, 2)
void gemm_qkv_kernel(const unsigned* __restrict__ xqh, const unsigned* __restrict__ xql,
                     const unsigned* __restrict__ xkh,
                     const unsigned* __restrict__ xvh,
                     const unsigned* __restrict__ wqh,
                     const unsigned* __restrict__ wkh,
                     const unsigned* __restrict__ wvh,
                     const float* __restrict__ bq, const float* __restrict__ bk,
                     const float* __restrict__ bv,
                     unsigned* __restrict__ qh, unsigned* __restrict__ ql,
                     unsigned* __restrict__ kh,
                     unsigned* __restrict__ vth)
{
    extern __shared__ unsigned sg[];

    const int z = blockIdx.z;
    const int t    = threadIdx.x;
    const int lane = t & 31;
    const int wid  = t >> 5;
    const int wm   = wid >> 2;
    const int wn   = wid & 3;
    const int g    = lane >> 2;
    const int tig  = lane & 3;
    const int m0 = blockIdx.y * 128;
    const int n0 = blockIdx.x * 128;

    float c[4][4][4];
#pragma unroll
    for (int i = 0; i < 4; ++i)
#pragma unroll
        for (int j = 0; j < 4; ++j)
#pragma unroll
            for (int e = 0; e < 4; ++e) c[i][j][e] = 0.0f;

    const float* bias;
    float scale;
    if (z == 0) {
        gemm_mainloop<true>(xqh, xql, wqh, m0, n0, sg, c);
        bias = bq; scale = SCALE_Q;
    } else if (z == 1) {
        gemm_mainloop<false>(xkh, nullptr, wkh, m0, n0, sg, c);
        bias = bk; scale = 1.0f;
    } else {
        gemm_mainloop<false>(xvh, nullptr, wvh, m0, n0, sg, c);
        bias = bv; scale = 1.0f;
    }

#pragma unroll
    for (int mf = 0; mf < 4; ++mf) {
#pragma unroll
        for (int nf = 0; nf < 4; ++nf) {
            int m = m0 + wm * 64 + mf * 16 + g;
            int n = n0 + wn * 32 + nf * 8 + tig * 2;
            float v0 = (c[mf][nf][0] + bias[n]) * scale;
            float v1 = (c[mf][nf][1] + bias[n + 1]) * scale;
            float v2 = (c[mf][nf][2] + bias[n]) * scale;
            float v3 = (c[mf][nf][3] + bias[n + 1]) * scale;
            int b = m >> 11, s = m & 2047;
            int h = n >> 6, hd = n & 63;
            if (z == 0) {
                unsigned hh, ll;
                split_pair_f16(v0, v1, hh, ll);
                size_t p0 = (((size_t)(b * Hc + h)) * Sc + s) * 32 + (hd >> 1);
                qh[p0] = hh; ql[p0] = ll;
                split_pair_f16(v2, v3, hh, ll);
                size_t p1 = (((size_t)(b * Hc + h)) * Sc + (s + 8)) * 32 + (hd >> 1);
                qh[p1] = hh; ql[p1] = ll;
            } else if (z == 1) {
                size_t p0 = (((size_t)(b * Hc + h)) * Sc + s) * 32 + (hd >> 1);
                size_t p1 = (((size_t)(b * Hc + h)) * Sc + (s + 8)) * 32 + (hd >> 1);
                kh[p0] = pack_f16(v0, v1);
                kh[p1] = pack_f16(v2, v3);
            } else {
                float p0 = __shfl_xor_sync(0xffffffffu, v0, 4);
                float p1 = __shfl_xor_sync(0xffffffffu, v1, 4);
                float p2 = __shfl_xor_sync(0xffffffffu, v2, 4);
                float p3 = __shfl_xor_sync(0xffffffffu, v3, 4);
                if (!(g & 1)) {
                    size_t rb = ((size_t)(b * Hc + h)) * 64;
                    int kp = s >> 1;
                    vth[(rb + hd) * 1024 + kp]         = pack_f16(v0, p0);
                    vth[(rb + hd + 1) * 1024 + kp]     = pack_f16(v1, p1);
                    vth[(rb + hd) * 1024 + kp + 4]     = pack_f16(v2, p2);
                    vth[(rb + hd + 1) * 1024 + kp + 4] = pack_f16(v3, p3);
                }
            }
        }
    }
}

// ---------------------------------------------------------------------------
// Output GEMM: ctx(single fp16) @ Wo(hi)^T + bo -> fp32 out (1-pass)
// ---------------------------------------------------------------------------
__global__ __launch_bounds__(256, 2)
void gemm_out_kernel(const unsigned* __restrict__ Xhi,
                     const unsigned* __restrict__ Whi,
                     const float* __restrict__ bias, float* __restrict__ outf)
{
    extern __shared__ unsigned sg[];

    const int t    = threadIdx.x;
    const int lane = t & 31;
    const int wid  = t >> 5;
    const int wm   = wid >> 2;
    const int wn   = wid & 3;
    const int g    = lane >> 2;
    const int tig  = lane & 3;
    const int m0 = blockIdx.y * 128;
    const int n0 = blockIdx.x * 128;

    float c[4][4][4];
#pragma unroll
    for (int i = 0; i < 4; ++i)
#pragma unroll
        for (int j = 0; j < 4; ++j)
#pragma unroll
            for (int e = 0; e < 4; ++e) c[i][j][e] = 0.0f;

    gemm_mainloop<false>(Xhi, nullptr, Whi, m0, n0, sg, c);

#pragma unroll
    for (int mf = 0; mf < 4; ++mf) {
#pragma unroll
        for (int nf = 0; nf < 4; ++nf) {
            int m = m0 + wm * 64 + mf * 16 + g;
            int n = n0 + wn * 32 + nf * 8 + tig * 2;
            outf[(size_t)m * Dc + n]           = c[mf][nf][0] + bias[n];
            outf[(size_t)m * Dc + n + 1]       = c[mf][nf][1] + bias[n + 1];
            outf[(size_t)(m + 8) * Dc + n]     = c[mf][nf][2] + bias[n];
            outf[(size_t)(m + 8) * Dc + n + 1] = c[mf][nf][3] + bias[n + 1];
        }
    }
}

// ---------------------------------------------------------------------------
// Flash attention: fp16 2-pass QK (Q split, K single), fp16 P, single-fp16 V
// 1-pass PV, exp2 softmax, cp.async double-buffered (Kh,Vh per stage).
// ---------------------------------------------------------------------------
#define AT_STAGE_U32 (2*64*36)
#define ATTN5_SMEM_U32 (2*128*36 + 2*AT_STAGE_U32)
#define ATTN5_SMEM_BYTES (ATTN5_SMEM_U32 * 4)   // 73728

__global__ __launch_bounds__(256, 2)
void attn_mma_kernel(const unsigned* __restrict__ Qhg, const unsigned* __restrict__ Qlg,
                     const unsigned* __restrict__ Khg,
                     const unsigned* __restrict__ Vthg,
                     unsigned* __restrict__ Chi)
{
    extern __shared__ unsigned smu[];
    unsigned* Qsh = smu;                    // [128][36]
    unsigned* Qsl = Qsh + 128 * 36;
    unsigned* stages = Qsl + 128 * 36;

    const int bh = blockIdx.y;
    const int qt = (int)(gridDim.x - 1 - blockIdx.x);
    const int q0 = qt * 128;
    const int t    = threadIdx.x;
    const int lane = t & 31;
    const int w    = t >> 5;
    const int g    = lane >> 2;
    const int tig  = lane & 3;

    const int agrp  = lane >> 3;
    const int l7    = lane & 7;
    const int a_row = l7 + ((agrp & 1) << 3);
    const int a_col = (agrp >> 1) << 2;
    const int b_row = l7 + ((agrp >> 1) << 3);
    const int b_col = (agrp & 1) << 2;

    const unsigned* Qbh = Qhg + (size_t)bh * Sc * 32;
    const unsigned* Qbl = Qlg + (size_t)bh * Sc * 32;
    const unsigned* Kbh = Khg + (size_t)bh * Sc * 32;
    const unsigned* Vbh = Vthg + (size_t)bh * 64 * 1024;

#pragma unroll
    for (int j = 0; j < 4; ++j) {
        int id = t + j * 256;
        int r = id >> 3, c4 = (id & 7) << 2;
        cp16(&Qsh[r * 36 + c4], &Qbh[(size_t)(q0 + r) * 32 + c4]);
        cp16(&Qsl[r * 36 + c4], &Qbl[(size_t)(q0 + r) * 32 + c4]);
    }
    asm volatile("cp.async.commit_group;\n" ::: "memory");

    auto stage_fn = [&](int st, int kt) {
        unsigned* Kh = stages + st * AT_STAGE_U32;
        unsigned* Vh = Kh + 64 * 36;
        const int k0 = kt * 64, kp0 = kt * 32;
#pragma unroll
        for (int j = 0; j < 2; ++j) {
            int id = t + j * 256;
            int r = id >> 3, c4 = (id & 7) << 2;
            cp16(Kh + r * 36 + c4, Kbh + (size_t)(k0 + r) * 32 + c4);
            cp16(Vh + r * 36 + c4, Vbh + (size_t)r * 1024 + kp0 + c4);
        }
        asm volatile("cp.async.commit_group;\n" ::: "memory");
    };

    float m_i[2] = {-1e30f, -1e30f};
    float l_i[2] = {0.0f, 0.0f};
    float o[8][4];
#pragma unroll
    for (int f = 0; f < 8; ++f)
#pragma unroll
        for (int e = 0; e < 4; ++e) o[f][e] = 0.0f;

    const int row0 = q0 + w * 16 + g;
    const int nkt = 2 * qt + 2;

    stage_fn(0, 0);

    for (int kt = 0; kt < nkt; ++kt) {
        const int k0 = kt * 64;
        __syncthreads();
        if (kt + 1 < nkt) {
            stage_fn((kt + 1) & 1, kt + 1);
            asm volatile("cp.async.wait_group 1;\n" ::: "memory");
        } else {
            asm volatile("cp.async.wait_group 0;\n" ::: "memory");
        }
        __syncthreads();

        if (q0 + w * 16 + 15 < k0) continue;

        const unsigned* Ksh = stages + (kt & 1) * AT_STAGE_U32;
        const unsigned* Vsh = Ksh + 64 * 36;

        // ---- S = Q K^T (fp16 2-pass: qh*kh + ql*kh) ----
        float s[8][4];
#pragma unroll
        for (int nf = 0; nf < 8; ++nf)
#pragma unroll
            for (int e = 0; e < 4; ++e) s[nf][e] = 0.0f;

#pragma unroll
        for (int ks = 0; ks < 4; ++ks) {
            unsigned aqh[4], aql[4];
            const int qoff = (w * 16 + a_row) * 36 + 8 * ks + a_col;
            ldsm4(aqh, Qsh + qoff);
            ldsm4(aql, Qsl + qoff);
            unsigned khi[4][4];
#pragma unroll
            for (int np = 0; np < 4; ++np) {
                const int koff = (np * 16 + b_row) * 36 + 8 * ks + b_col;
                ldsm4(khi[np], Ksh + koff);
            }
#pragma unroll
            for (int nf = 0; nf < 8; ++nf)
                mma16816f16(s[nf], aqh, &khi[nf >> 1][(nf & 1) * 2]);
#pragma unroll
            for (int nf = 0; nf < 8; ++nf)
                mma16816f16(s[nf], aql, &khi[nf >> 1][(nf & 1) * 2]);
        }

        // ---- causal mask ----
        if (k0 + 63 > q0 + w * 16) {
#pragma unroll
            for (int nf = 0; nf < 8; ++nf) {
                int key = k0 + 8 * nf + 2 * tig;
                if (key     > row0)     s[nf][0] = -1e30f;
                if (key + 1 > row0)     s[nf][1] = -1e30f;
                if (key     > row0 + 8) s[nf][2] = -1e30f;
                if (key + 1 > row0 + 8) s[nf][3] = -1e30f;
            }
        }

        // ---- online softmax (base-2 domain) ----
        float mx0 = -1e30f, mx1 = -1e30f;
#pragma unroll
        for (int nf = 0; nf < 8; ++nf) {
            mx0 = fmaxf(mx0, fmaxf(s[nf][0], s[nf][1]));
            mx1 = fmaxf(mx1, fmaxf(s[nf][2], s[nf][3]));
        }
        mx0 = fmaxf(mx0, __shfl_xor_sync(0xffffffffu, mx0, 1));
        mx0 = fmaxf(mx0, __shfl_xor_sync(0xffffffffu, mx0, 2));
        mx1 = fmaxf(mx1, __shfl_xor_sync(0xffffffffu, mx1, 1));
        mx1 = fmaxf(mx1, __shfl_xor_sync(0xffffffffu, mx1, 2));

        float mn0 = fmaxf(m_i[0], mx0);
        float mn1 = fmaxf(m_i[1], mx1);
        float cs0 = exp2f(m_i[0] - mn0);
        float cs1 = exp2f(m_i[1] - mn1);
        m_i[0] = mn0; m_i[1] = mn1;

        unsigned pf[8][2];
        float sum0 = 0.0f, sum1 = 0.0f;
#pragma unroll
        for (int nf = 0; nf < 8; ++nf) {
            float p0 = exp2f(s[nf][0] - mn0);
            float p1 = exp2f(s[nf][1] - mn0);
            float p2 = exp2f(s[nf][2] - mn1);
            float p3 = exp2f(s[nf][3] - mn1);
            sum0 += p0 + p1;
            sum1 += p2 + p3;
            pf[nf][0] = pack_f16(p0, p1);
            pf[nf][1] = pack_f16(p2, p3);
        }
        sum0 += __shfl_xor_sync(0xffffffffu, sum0, 1);
        sum0 += __shfl_xor_sync(0xffffffffu, sum0, 2);
        sum1 += __shfl_xor_sync(0xffffffffu, sum1, 1);
        sum1 += __shfl_xor_sync(0xffffffffu, sum1, 2);
        l_i[0] = l_i[0] * cs0 + sum0;
        l_i[1] = l_i[1] * cs1 + sum1;

#pragma unroll
        for (int f = 0; f < 8; ++f) {
            o[f][0] *= cs0; o[f][1] *= cs0;
            o[f][2] *= cs1; o[f][3] *= cs1;
        }

        // ---- O += P V (fp16, 1-pass) ----
#pragma unroll
        for (int ks = 0; ks < 4; ++ks) {
            unsigned pa[4] = { pf[2 * ks][0], pf[2 * ks][1],
                               pf[2 * ks + 1][0], pf[2 * ks + 1][1] };
            unsigned vhi[4][4];
#pragma unroll
            for (int np = 0; np < 4; ++np) {
                const int voff = (np * 16 + b_row) * 36 + 8 * ks + b_col;
                ldsm4(vhi[np], Vsh + voff);
            }
#pragma unroll
            for (int nf = 0; nf < 8; ++nf)
                mma16816f16(o[nf], pa, &vhi[nf >> 1][(nf & 1) * 2]);
        }
    }

    // ---- epilogue: normalize, single fp16, write ctx ----
    const float inv0 = 1.0f / l_i[0];
    const float inv1 = 1.0f / l_i[1];
    const int b = bh >> 4;
    const int h = bh & 15;
#pragma unroll
    for (int nf = 0; nf < 8; ++nf) {
        int col = 8 * nf + 2 * tig;
        size_t p0 = ((size_t)b * Sc + row0) * 512 + h * 32 + (col >> 1);
        size_t p1 = ((size_t)b * Sc + row0 + 8) * 512 + h * 32 + (col >> 1);
        Chi[p0] = pack_f16(o[nf][0] * inv0, o[nf][1] * inv0);
        Chi[p1] = pack_f16(o[nf][2] * inv1, o[nf][3] * inv1);
    }
}

// ---------------------------------------------------------------------------
// Launch
// ---------------------------------------------------------------------------
#define SYMADDR(p, s) do { void* _tmp; cudaGetSymbolAddress(&_tmp, s); p = (unsigned*)_tmp; } while (0)

extern "C" void kernel_launch(void* const* d_in, const int* in_sizes, int n_in,
                              void* d_out, int out_size)
{
    const float* q  = (const float*)d_in[0];
    const float* k  = (const float*)d_in[1];
    const float* v  = (const float*)d_in[2];
    const float* Wq = (const float*)d_in[4];
    const float* bq = (const float*)d_in[5];
    const float* Wk = (const float*)d_in[6];
    const float* bk = (const float*)d_in[7];
    const float* Wv = (const float*)d_in[8];
    const float* bv = (const float*)d_in[9];
    const float* Wo = (const float*)d_in[10];
    const float* bo = (const float*)d_in[11];
    float* out = (float*)d_out;

    unsigned *wqh,*wkh,*wvh,*woh;
    unsigned *xqh,*xql,*xkh,*xvh;
    unsigned *qh,*ql,*kh,*vth,*ch;
    SYMADDR(wqh, g_Wqhi); SYMADDR(wkh, g_Wkhi);
    SYMADDR(wvh, g_Wvhi); SYMADDR(woh, g_Wohi);
    SYMADDR(xqh, g_Xqhi); SYMADDR(xql, g_Xqlo);
    SYMADDR(xkh, g_Xkhi); SYMADDR(xvh, g_Xvhi);
    SYMADDR(qh, g_Qhi);   SYMADDR(ql, g_Qlo);
    SYMADDR(kh, g_Khi);
    SYMADDR(vth, g_Vthi);
    SYMADDR(ch, g_Chi);

    cudaFuncSetAttribute(gemm_qkv_kernel, cudaFuncAttributeMaxDynamicSharedMemorySize, GEMM_SMEM);
    cudaFuncSetAttribute(gemm_out_kernel, cudaFuncAttributeMaxDynamicSharedMemorySize, GEMM_SMEM);
    cudaFuncSetAttribute(attn_mma_kernel, cudaFuncAttributeMaxDynamicSharedMemorySize, ATTN5_SMEM_BYTES);

    // q: full hi/lo split; weights + k + v inputs: hi only (batched)
    split_hl_kernel<<<8192, 256>>>((const float4*)q, (uint2*)xqh, (uint2*)xql);
    split_hi6_kernel<<<dim3(8192, 6), 256>>>(
        (const float4*)Wq, (const float4*)Wk, (const float4*)Wv, (const float4*)Wo,
        (const float4*)k, (const float4*)v,
        (uint2*)wqh, (uint2*)wkh, (uint2*)wvh, (uint2*)woh,
        (uint2*)xkh, (uint2*)xvh, 4);

    dim3 gg3(Dc / 128, Mrows / 128, 3);   // (8, 64, 3)
    gemm_qkv_kernel<<<gg3, 256, GEMM_SMEM>>>(
        xqh, xql, xkh, xvh,
        wqh, wkh, wvh,
        bq, bk, bv,
        qh, ql, kh, vth);

    dim3 ga(Sc / 128, Bc * Hc);           // (16, 64)
    attn_mma_kernel<<<ga, 256, ATTN5_SMEM_BYTES>>>(qh, ql, kh, vth, ch);

    dim3 gg(Dc / 128, Mrows / 128);       // (8, 64)
    gemm_out_kernel<<<gg, 256, GEMM_SMEM>>>(ch, woh, bo, out);
}

// round 16
// speedup vs baseline: 1.5991x; 1.2022x over previous
#include <cuda_runtime.h>
#include <cuda_bf16.h>
#include <cuda_fp16.h>

// Problem constants
#define Bc 4
#define Sc 2048
#define Dc 1024
#define Hc 16
#define Mrows (Bc*Sc)   // 8192

#define SCALE_Q 0.18033688010819965f   // 0.125 * log2(e)

// ---------------------------------------------------------------------------
// Device scratch (u32 = packed pair of fp16), all single-plane fp16
// ---------------------------------------------------------------------------
__device__ unsigned g_Wqhi[1024*512];
__device__ unsigned g_Wkhi[1024*512];
__device__ unsigned g_Wvhi[1024*512];
__device__ unsigned g_Wohi[1024*512];
__device__ unsigned g_Xqhi[(size_t)Mrows*512];
__device__ unsigned g_Xkhi[(size_t)Mrows*512];
__device__ unsigned g_Xvhi[(size_t)Mrows*512];
// Q/K head layout [B,H,S,32] single fp16
__device__ unsigned g_Qhi[(size_t)Mrows*512];
__device__ unsigned g_Khi[(size_t)Mrows*512];
// V transposed head layout [B,H,64(hd),1024(key-pair)] single fp16
__device__ unsigned g_Vthi[(size_t)Mrows*512];
// ctx [B,S,512] single fp16
__device__ unsigned g_Chi[(size_t)Mrows*512];

// ---------------------------------------------------------------------------
// Helpers
// ---------------------------------------------------------------------------
__device__ __forceinline__ unsigned pack_f16(float x0, float x1)
{
    __half2 h2 = __floats2half2_rn(x0, x1);
    return *reinterpret_cast<unsigned*>(&h2);
}

__device__ __forceinline__ void mma16816f16(float c[4], const unsigned a[4],
                                            const unsigned b[2])
{
    asm volatile(
        "mma.sync.aligned.m16n8k16.row.col.f32.f16.f16.f32 "
        "{%0,%1,%2,%3}, {%4,%5,%6,%7}, {%8,%9}, {%0,%1,%2,%3};\n"
        : "+f"(c[0]), "+f"(c[1]), "+f"(c[2]), "+f"(c[3])
        : "r"(a[0]), "r"(a[1]), "r"(a[2]), "r"(a[3]),
          "r"(b[0]), "r"(b[1]));
}

__device__ __forceinline__ void ldsm4(unsigned r[4], const unsigned* p)
{
    unsigned a = (unsigned)__cvta_generic_to_shared(p);
    asm volatile("ldmatrix.sync.aligned.m8n8.x4.shared.b16 {%0,%1,%2,%3}, [%4];\n"
                 : "=r"(r[0]), "=r"(r[1]), "=r"(r[2]), "=r"(r[3]) : "r"(a));
}

__device__ __forceinline__ void cp16(void* smem, const void* g)
{
    unsigned sa = (unsigned)__cvta_generic_to_shared(smem);
    asm volatile("cp.async.cg.shared.global [%0], [%1], 16;\n"
                 :: "r"(sa), "l"(g) : "memory");
}

// ---------------------------------------------------------------------------
// Batched fp16 converter over up to 7 matrices (first n_small are 1024-block)
// ---------------------------------------------------------------------------
__global__ __launch_bounds__(256)
void split_hi7_kernel(const float4* __restrict__ i0, const float4* __restrict__ i1,
                      const float4* __restrict__ i2, const float4* __restrict__ i3,
                      const float4* __restrict__ i4, const float4* __restrict__ i5,
                      const float4* __restrict__ i6,
                      uint2* __restrict__ o0, uint2* __restrict__ o1,
                      uint2* __restrict__ o2, uint2* __restrict__ o3,
                      uint2* __restrict__ o4, uint2* __restrict__ o5,
                      uint2* __restrict__ o6,
                      int n_small)
{
    const float4* in; uint2* out;
    switch (blockIdx.y) {
        case 0:  in = i0; out = o0; break;
        case 1:  in = i1; out = o1; break;
        case 2:  in = i2; out = o2; break;
        case 3:  in = i3; out = o3; break;
        case 4:  in = i4; out = o4; break;
        case 5:  in = i5; out = o5; break;
        default: in = i6; out = o6; break;
    }
    int nblk = ((int)blockIdx.y < n_small) ? 1024 : 8192;
    if (blockIdx.x >= (unsigned)nblk) return;
    int i = blockIdx.x * 256 + threadIdx.x;
    float4 f = in[i];
    out[i] = make_uint2(pack_f16(f.x, f.y), pack_f16(f.z, f.w));
}

// ---------------------------------------------------------------------------
// Shared GEMM mainloop: fp16 1-pass (X hi, W hi), 2-stage cp.async pipeline,
// ldmatrix fragments.
// ---------------------------------------------------------------------------
#define KPAD 20
#define HALF_U32 (128*KPAD)
#define STAGE_U32 (2*HALF_U32)
#define GEMM_SMEM (2*STAGE_U32*4)   // 40960 bytes

__device__ __forceinline__ void gemm_mainloop(
    const unsigned* __restrict__ Xhi,
    const unsigned* __restrict__ Whi,
    int m0, int n0, unsigned* sg, float c[4][4][4])
{
    const int t    = threadIdx.x;
    const int lane = t & 31;
    const int wid  = t >> 5;
    const int wm   = wid >> 2;
    const int wn   = wid & 3;

    const int agrp  = lane >> 3;
    const int l7    = lane & 7;
    const int a_row = l7 + ((agrp & 1) << 3);
    const int a_col = (agrp >> 1) << 2;
    const int b_row = l7 + ((agrp >> 1) << 3);
    const int b_col = (agrp & 1) << 2;

    auto issue = [&](int stage, int kt) {
        unsigned* base = sg + stage * STAGE_U32;
#pragma unroll
        for (int j = 0; j < 4; ++j) {
            int id   = t + j * 256;
            int half = id >> 9;              // 0..1
            int rem  = id & 511;
            int row  = rem >> 2;
            int c4   = (rem & 3) << 2;
            const unsigned* src;
            if (half == 0) src = Xhi + (size_t)(m0 + row) * 512 + kt * 16 + c4;
            else           src = Whi + (size_t)(n0 + row) * 512 + kt * 16 + c4;
            cp16(base + half * HALF_U32 + row * KPAD + c4, src);
        }
        asm volatile("cp.async.commit_group;\n" ::: "memory");
    };

    issue(0, 0);

    const int NT = 32;
    for (int kt = 0; kt < NT; ++kt) {
        if (kt + 1 < NT) {
            issue((kt + 1) & 1, kt + 1);
            asm volatile("cp.async.wait_group 1;\n" ::: "memory");
        } else {
            asm volatile("cp.async.wait_group 0;\n" ::: "memory");
        }
        __syncthreads();

        const unsigned* Ah = sg + (kt & 1) * STAGE_U32;
        const unsigned* Bh = Ah + HALF_U32;

#pragma unroll
        for (int ks = 0; ks < 2; ++ks) {
            const int pb = ks * 8;
            unsigned ahi[4][4], bhi[2][4];
#pragma unroll
            for (int mf = 0; mf < 4; ++mf) {
                const int r = (wm * 64 + mf * 16 + a_row) * KPAD + pb + a_col;
                ldsm4(ahi[mf], Ah + r);
            }
#pragma unroll
            for (int np = 0; np < 2; ++np) {
                const int r = (wn * 32 + np * 16 + b_row) * KPAD + pb + b_col;
                ldsm4(bhi[np], Bh + r);
            }
#pragma unroll
            for (int mf = 0; mf < 4; ++mf)
#pragma unroll
                for (int nf = 0; nf < 4; ++nf)
                    mma16816f16(c[mf][nf], ahi[mf], &bhi[nf >> 1][(nf & 1) * 2]);
        }
        __syncthreads();
    }
}

// ---------------------------------------------------------------------------
// Merged Q/K/V projection GEMM: z=0 Q (single fp16 out, scaled),
// z=1 K (single fp16 out), z=2 V (transposed single fp16 out). All 1-pass.
// ---------------------------------------------------------------------------
__global__ __launch_bounds__(256, 2)
void gemm_qkv_kernel(const unsigned* __restrict__ xqh,
                     const unsigned* __restrict__ xkh,
                     const unsigned* __restrict__ xvh,
                     const unsigned* __restrict__ wqh,
                     const unsigned* __restrict__ wkh,
                     const unsigned* __restrict__ wvh,
                     const float* __restrict__ bq, const float* __restrict__ bk,
                     const float* __restrict__ bv,
                     unsigned* __restrict__ qh,
                     unsigned* __restrict__ kh,
                     unsigned* __restrict__ vth)
{
    extern __shared__ unsigned sg[];

    const int z = blockIdx.z;
    const unsigned *Xhi, *Whi;
    const float* bias;
    float scale;
    if (z == 0) { Xhi = xqh; Whi = wqh; bias = bq; scale = SCALE_Q; }
    else if (z == 1) { Xhi = xkh; Whi = wkh; bias = bk; scale = 1.0f; }
    else { Xhi = xvh; Whi = wvh; bias = bv; scale = 1.0f; }

    const int t    = threadIdx.x;
    const int lane = t & 31;
    const int wid  = t >> 5;
    const int wm   = wid >> 2;
    const int wn   = wid & 3;
    const int g    = lane >> 2;
    const int tig  = lane & 3;
    const int m0 = blockIdx.y * 128;
    const int n0 = blockIdx.x * 128;

    float c[4][4][4];
#pragma unroll
    for (int i = 0; i < 4; ++i)
#pragma unroll
        for (int j = 0; j < 4; ++j)
#pragma unroll
            for (int e = 0; e < 4; ++e) c[i][j][e] = 0.0f;

    gemm_mainloop(Xhi, Whi, m0, n0, sg, c);

#pragma unroll
    for (int mf = 0; mf < 4; ++mf) {
#pragma unroll
        for (int nf = 0; nf < 4; ++nf) {
            int m = m0 + wm * 64 + mf * 16 + g;
            int n = n0 + wn * 32 + nf * 8 + tig * 2;
            float v0 = (c[mf][nf][0] + bias[n]) * scale;
            float v1 = (c[mf][nf][1] + bias[n + 1]) * scale;
            float v2 = (c[mf][nf][2] + bias[n]) * scale;
            float v3 = (c[mf][nf][3] + bias[n + 1]) * scale;
            int b = m >> 11, s = m & 2047;
            int h = n >> 6, hd = n & 63;
            if (z < 2) {
                unsigned* dst = (z == 0) ? qh : kh;
                size_t p0 = (((size_t)(b * Hc + h)) * Sc + s) * 32 + (hd >> 1);
                size_t p1 = (((size_t)(b * Hc + h)) * Sc + (s + 8)) * 32 + (hd >> 1);
                dst[p0] = pack_f16(v0, v1);
                dst[p1] = pack_f16(v2, v3);
            } else {
                float p0 = __shfl_xor_sync(0xffffffffu, v0, 4);
                float p1 = __shfl_xor_sync(0xffffffffu, v1, 4);
                float p2 = __shfl_xor_sync(0xffffffffu, v2, 4);
                float p3 = __shfl_xor_sync(0xffffffffu, v3, 4);
                if (!(g & 1)) {
                    size_t rb = ((size_t)(b * Hc + h)) * 64;
                    int kp = s >> 1;
                    vth[(rb + hd) * 1024 + kp]         = pack_f16(v0, p0);
                    vth[(rb + hd + 1) * 1024 + kp]     = pack_f16(v1, p1);
                    vth[(rb + hd) * 1024 + kp + 4]     = pack_f16(v2, p2);
                    vth[(rb + hd + 1) * 1024 + kp + 4] = pack_f16(v3, p3);
                }
            }
        }
    }
}

// ---------------------------------------------------------------------------
// Output GEMM: ctx(single fp16) @ Wo(hi)^T + bo -> fp32 out (1-pass)
// ---------------------------------------------------------------------------
__global__ __launch_bounds__(256, 2)
void gemm_out_kernel(const unsigned* __restrict__ Xhi,
                     const unsigned* __restrict__ Whi,
                     const float* __restrict__ bias, float* __restrict__ outf)
{
    extern __shared__ unsigned sg[];

    const int t    = threadIdx.x;
    const int lane = t & 31;
    const int wid  = t >> 5;
    const int wm   = wid >> 2;
    const int wn   = wid & 3;
    const int g    = lane >> 2;
    const int tig  = lane & 3;
    const int m0 = blockIdx.y * 128;
    const int n0 = blockIdx.x * 128;

    float c[4][4][4];
#pragma unroll
    for (int i = 0; i < 4; ++i)
#pragma unroll
        for (int j = 0; j < 4; ++j)
#pragma unroll
            for (int e = 0; e < 4; ++e) c[i][j][e] = 0.0f;

    gemm_mainloop(Xhi, Whi, m0, n0, sg, c);

#pragma unroll
    for (int mf = 0; mf < 4; ++mf) {
#pragma unroll
        for (int nf = 0; nf < 4; ++nf) {
            int m = m0 + wm * 64 + mf * 16 + g;
            int n = n0 + wn * 32 + nf * 8 + tig * 2;
            outf[(size_t)m * Dc + n]           = c[mf][nf][0] + bias[n];
            outf[(size_t)m * Dc + n + 1]       = c[mf][nf][1] + bias[n + 1];
            outf[(size_t)(m + 8) * Dc + n]     = c[mf][nf][2] + bias[n];
            outf[(size_t)(m + 8) * Dc + n + 1] = c[mf][nf][3] + bias[n + 1];
        }
    }
}

// ---------------------------------------------------------------------------
// Flash attention: fp16 1-pass QK, fp16 P, single-fp16 V 1-pass PV,
// exp2 softmax, cp.async double-buffered (Kh,Vh per stage).
// ---------------------------------------------------------------------------
#define AT_STAGE_U32 (2*64*36)
#define ATTN6_SMEM_U32 (128*36 + 2*AT_STAGE_U32)
#define ATTN6_SMEM_BYTES (ATTN6_SMEM_U32 * 4)   // 55296

__global__ __launch_bounds__(256, 2)
void attn_mma_kernel(const unsigned* __restrict__ Qhg,
                     const unsigned* __restrict__ Khg,
                     const unsigned* __restrict__ Vthg,
                     unsigned* __restrict__ Chi)
{
    extern __shared__ unsigned smu[];
    unsigned* Qsh = smu;                    // [128][36]
    unsigned* stages = Qsh + 128 * 36;

    const int bh = blockIdx.y;
    const int qt = (int)(gridDim.x - 1 - blockIdx.x);
    const int q0 = qt * 128;
    const int t    = threadIdx.x;
    const int lane = t & 31;
    const int w    = t >> 5;
    const int g    = lane >> 2;
    const int tig  = lane & 3;

    const int agrp  = lane >> 3;
    const int l7    = lane & 7;
    const int a_row = l7 + ((agrp & 1) << 3);
    const int a_col = (agrp >> 1) << 2;
    const int b_row = l7 + ((agrp >> 1) << 3);
    const int b_col = (agrp & 1) << 2;

    const unsigned* Qbh = Qhg + (size_t)bh * Sc * 32;
    const unsigned* Kbh = Khg + (size_t)bh * Sc * 32;
    const unsigned* Vbh = Vthg + (size_t)bh * 64 * 1024;

#pragma unroll
    for (int j = 0; j < 4; ++j) {
        int id = t + j * 256;
        int r = id >> 3, c4 = (id & 7) << 2;
        cp16(&Qsh[r * 36 + c4], &Qbh[(size_t)(q0 + r) * 32 + c4]);
    }
    asm volatile("cp.async.commit_group;\n" ::: "memory");

    auto stage_fn = [&](int st, int kt) {
        unsigned* Kh = stages + st * AT_STAGE_U32;
        unsigned* Vh = Kh + 64 * 36;
        const int k0 = kt * 64, kp0 = kt * 32;
#pragma unroll
        for (int j = 0; j < 2; ++j) {
            int id = t + j * 256;
            int r = id >> 3, c4 = (id & 7) << 2;
            cp16(Kh + r * 36 + c4, Kbh + (size_t)(k0 + r) * 32 + c4);
            cp16(Vh + r * 36 + c4, Vbh + (size_t)r * 1024 + kp0 + c4);
        }
        asm volatile("cp.async.commit_group;\n" ::: "memory");
    };

    float m_i[2] = {-1e30f, -1e30f};
    float l_i[2] = {0.0f, 0.0f};
    float o[8][4];
#pragma unroll
    for (int f = 0; f < 8; ++f)
#pragma unroll
        for (int e = 0; e < 4; ++e) o[f][e] = 0.0f;

    const int row0 = q0 + w * 16 + g;
    const int nkt = 2 * qt + 2;

    stage_fn(0, 0);

    for (int kt = 0; kt < nkt; ++kt) {
        const int k0 = kt * 64;
        __syncthreads();
        if (kt + 1 < nkt) {
            stage_fn((kt + 1) & 1, kt + 1);
            asm volatile("cp.async.wait_group 1;\n" ::: "memory");
        } else {
            asm volatile("cp.async.wait_group 0;\n" ::: "memory");
        }
        __syncthreads();

        if (q0 + w * 16 + 15 < k0) continue;

        const unsigned* Ksh = stages + (kt & 1) * AT_STAGE_U32;
        const unsigned* Vsh = Ksh + 64 * 36;

        // ---- S = Q K^T (fp16 1-pass) ----
        float s[8][4];
#pragma unroll
        for (int nf = 0; nf < 8; ++nf)
#pragma unroll
            for (int e = 0; e < 4; ++e) s[nf][e] = 0.0f;

#pragma unroll
        for (int ks = 0; ks < 4; ++ks) {
            unsigned aq[4];
            const int qoff = (w * 16 + a_row) * 36 + 8 * ks + a_col;
            ldsm4(aq, Qsh + qoff);
            unsigned khi[4][4];
#pragma unroll
            for (int np = 0; np < 4; ++np) {
                const int koff = (np * 16 + b_row) * 36 + 8 * ks + b_col;
                ldsm4(khi[np], Ksh + koff);
            }
#pragma unroll
            for (int nf = 0; nf < 8; ++nf)
                mma16816f16(s[nf], aq, &khi[nf >> 1][(nf & 1) * 2]);
        }

        // ---- causal mask ----
        if (k0 + 63 > q0 + w * 16) {
#pragma unroll
            for (int nf = 0; nf < 8; ++nf) {
                int key = k0 + 8 * nf + 2 * tig;
                if (key     > row0)     s[nf][0] = -1e30f;
                if (key + 1 > row0)     s[nf][1] = -1e30f;
                if (key     > row0 + 8) s[nf][2] = -1e30f;
                if (key + 1 > row0 + 8) s[nf][3] = -1e30f;
            }
        }

        // ---- online softmax (base-2 domain) ----
        float mx0 = -1e30f, mx1 = -1e30f;
#pragma unroll
        for (int nf = 0; nf < 8; ++nf) {
            mx0 = fmaxf(mx0, fmaxf(s[nf][0], s[nf][1]));
            mx1 = fmaxf(mx1, fmaxf(s[nf][2], s[nf][3]));
        }
        mx0 = fmaxf(mx0, __shfl_xor_sync(0xffffffffu, mx0, 1));
        mx0 = fmaxf(mx0, __shfl_xor_sync(0xffffffffu, mx0, 2));
        mx1 = fmaxf(mx1, __shfl_xor_sync(0xffffffffu, mx1, 1));
        mx1 = fmaxf(mx1, __shfl_xor_sync(0xffffffffu, mx1, 2));

        float mn0 = fmaxf(m_i[0], mx0);
        float mn1 = fmaxf(m_i[1], mx1);
        float cs0 = exp2f(m_i[0] - mn0);
        float cs1 = exp2f(m_i[1] - mn1);
        m_i[0] = mn0; m_i[1] = mn1;

        unsigned pf[8][2];
        float sum0 = 0.0f, sum1 = 0.0f;
#pragma unroll
        for (int nf = 0; nf < 8; ++nf) {
            float p0 = exp2f(s[nf][0] - mn0);
            float p1 = exp2f(s[nf][1] - mn0);
            float p2 = exp2f(s[nf][2] - mn1);
            float p3 = exp2f(s[nf][3] - mn1);
            sum0 += p0 + p1;
            sum1 += p2 + p3;
            pf[nf][0] = pack_f16(p0, p1);
            pf[nf][1] = pack_f16(p2, p3);
        }
        sum0 += __shfl_xor_sync(0xffffffffu, sum0, 1);
        sum0 += __shfl_xor_sync(0xffffffffu, sum0, 2);
        sum1 += __shfl_xor_sync(0xffffffffu, sum1, 1);
        sum1 += __shfl_xor_sync(0xffffffffu, sum1, 2);
        l_i[0] = l_i[0] * cs0 + sum0;
        l_i[1] = l_i[1] * cs1 + sum1;

#pragma unroll
        for (int f = 0; f < 8; ++f) {
            o[f][0] *= cs0; o[f][1] *= cs0;
            o[f][2] *= cs1; o[f][3] *= cs1;
        }

        // ---- O += P V (fp16, 1-pass) ----
#pragma unroll
        for (int ks = 0; ks < 4; ++ks) {
            unsigned pa[4] = { pf[2 * ks][0], pf[2 * ks][1],
                               pf[2 * ks + 1][0], pf[2 * ks + 1][1] };
            unsigned vhi[4][4];
#pragma unroll
            for (int np = 0; np < 4; ++np) {
                const int voff = (np * 16 + b_row) * 36 + 8 * ks + b_col;
                ldsm4(vhi[np], Vsh + voff);
            }
#pragma unroll
            for (int nf = 0; nf < 8; ++nf)
                mma16816f16(o[nf], pa, &vhi[nf >> 1][(nf & 1) * 2]);
        }
    }

    // ---- epilogue: normalize, single fp16, write ctx ----
    const float inv0 = 1.0f / l_i[0];
    const float inv1 = 1.0f / l_i[1];
    const int b = bh >> 4;
    const int h = bh & 15;
#pragma unroll
    for (int nf = 0; nf < 8; ++nf) {
        int col = 8 * nf + 2 * tig;
        size_t p0 = ((size_t)b * Sc + row0) * 512 + h * 32 + (col >> 1);
        size_t p1 = ((size_t)b * Sc + row0 + 8) * 512 + h * 32 + (col >> 1);
        Chi[p0] = pack_f16(o[nf][0] * inv0, o[nf][1] * inv0);
        Chi[p1] = pack_f16(o[nf][2] * inv1, o[nf][3] * inv1);
    }
}

// ---------------------------------------------------------------------------
// Launch
// ---------------------------------------------------------------------------
#define SYMADDR(p, s) do { void* _tmp; cudaGetSymbolAddress(&_tmp, s); p = (unsigned*)_tmp; } while (0)

extern "C" void kernel_launch(void* const* d_in, const int* in_sizes, int n_in,
                              void* d_out, int out_size)
{
    const float* q  = (const float*)d_in[0];
    const float* k  = (const float*)d_in[1];
    const float* v  = (const float*)d_in[2];
    const float* Wq = (const float*)d_in[4];
    const float* bq = (const float*)d_in[5];
    const float* Wk = (const float*)d_in[6];
    const float* bk = (const float*)d_in[7];
    const float* Wv = (const float*)d_in[8];
    const float* bv = (const float*)d_in[9];
    const float* Wo = (const float*)d_in[10];
    const float* bo = (const float*)d_in[11];
    float* out = (float*)d_out;

    unsigned *wqh,*wkh,*wvh,*woh;
    unsigned *xqh,*xkh,*xvh;
    unsigned *qh,*kh,*vth,*ch;
    SYMADDR(wqh, g_Wqhi); SYMADDR(wkh, g_Wkhi);
    SYMADDR(wvh, g_Wvhi); SYMADDR(woh, g_Wohi);
    SYMADDR(xqh, g_Xqhi); SYMADDR(xkh, g_Xkhi); SYMADDR(xvh, g_Xvhi);
    SYMADDR(qh, g_Qhi);   SYMADDR(kh, g_Khi);
    SYMADDR(vth, g_Vthi);
    SYMADDR(ch, g_Chi);

    cudaFuncSetAttribute(gemm_qkv_kernel, cudaFuncAttributeMaxDynamicSharedMemorySize, GEMM_SMEM);
    cudaFuncSetAttribute(gemm_out_kernel, cudaFuncAttributeMaxDynamicSharedMemorySize, GEMM_SMEM);
    cudaFuncSetAttribute(attn_mma_kernel, cudaFuncAttributeMaxDynamicSharedMemorySize, ATTN6_SMEM_BYTES);

    // All conversions in one batched launch (4 weights small, 3 inputs large)
    split_hi7_kernel<<<dim3(8192, 7), 256>>>(
        (const float4*)Wq, (const float4*)Wk, (const float4*)Wv, (const float4*)Wo,
        (const float4*)q, (const float4*)k, (const float4*)v,
        (uint2*)wqh, (uint2*)wkh, (uint2*)wvh, (uint2*)woh,
        (uint2*)xqh, (uint2*)xkh, (uint2*)xvh, 4);

    dim3 gg3(Dc / 128, Mrows / 128, 3);   // (8, 64, 3)
    gemm_qkv_kernel<<<gg3, 256, GEMM_SMEM>>>(
        xqh, xkh, xvh,
        wqh, wkh, wvh,
        bq, bk, bv,
        qh, kh, vth);

    dim3 ga(Sc / 128, Bc * Hc);           // (16, 64)
    attn_mma_kernel<<<ga, 256, ATTN6_SMEM_BYTES>>>(qh, kh, vth, ch);

    dim3 gg(Dc / 128, Mrows / 128);       // (8, 64)
    gemm_out_kernel<<<gg, 256, GEMM_SMEM>>>(ch, woh, bo, out);
}

// round 17
// speedup vs baseline: 1.6779x; 1.0493x over previous
#include <cuda_runtime.h>
#include <cuda_bf16.h>
#include <cuda_fp16.h>

// Problem constants
#define Bc 4
#define Sc 2048
#define Dc 1024
#define Hc 16
#define Mrows (Bc*Sc)   // 8192

#define SCALE_Q 0.18033688010819965f   // 0.125 * log2(e)

// ---------------------------------------------------------------------------
// Device scratch (u32 = packed pair of fp16), all single-plane fp16
// ---------------------------------------------------------------------------
__device__ unsigned g_Wqhi[1024*512];
__device__ unsigned g_Wkhi[1024*512];
__device__ unsigned g_Wvhi[1024*512];
__device__ unsigned g_Wohi[1024*512];
__device__ unsigned g_Xqhi[(size_t)Mrows*512];
__device__ unsigned g_Xkhi[(size_t)Mrows*512];
__device__ unsigned g_Xvhi[(size_t)Mrows*512];
// Q/K head layout [B,H,S,32] single fp16
__device__ unsigned g_Qhi[(size_t)Mrows*512];
__device__ unsigned g_Khi[(size_t)Mrows*512];
// V transposed head layout [B,H,64(hd),1024(key-pair)] single fp16
__device__ unsigned g_Vthi[(size_t)Mrows*512];
// ctx [B,S,512] single fp16
__device__ unsigned g_Chi[(size_t)Mrows*512];

// ---------------------------------------------------------------------------
// Helpers
// ---------------------------------------------------------------------------
__device__ __forceinline__ unsigned pack_f16(float x0, float x1)
{
    __half2 h2 = __floats2half2_rn(x0, x1);
    return *reinterpret_cast<unsigned*>(&h2);
}

// 2^a, 2^b as packed fp16 pair via one MUFU op
__device__ __forceinline__ unsigned ex2_f16x2(float a, float b)
{
    __half2 h = __floats2half2_rn(a, b);
    unsigned hu = *reinterpret_cast<unsigned*>(&h);
    unsigned r;
    asm("ex2.approx.f16x2 %0, %1;" : "=r"(r) : "r"(hu));
    return r;
}

__device__ __forceinline__ void mma16816f16(float c[4], const unsigned a[4],
                                            const unsigned b[2])
{
    asm volatile(
        "mma.sync.aligned.m16n8k16.row.col.f32.f16.f16.f32 "
        "{%0,%1,%2,%3}, {%4,%5,%6,%7}, {%8,%9}, {%0,%1,%2,%3};\n"
        : "+f"(c[0]), "+f"(c[1]), "+f"(c[2]), "+f"(c[3])
        : "r"(a[0]), "r"(a[1]), "r"(a[2]), "r"(a[3]),
          "r"(b[0]), "r"(b[1]));
}

__device__ __forceinline__ void ldsm4(unsigned r[4], const unsigned* p)
{
    unsigned a = (unsigned)__cvta_generic_to_shared(p);
    asm volatile("ldmatrix.sync.aligned.m8n8.x4.shared.b16 {%0,%1,%2,%3}, [%4];\n"
                 : "=r"(r[0]), "=r"(r[1]), "=r"(r[2]), "=r"(r[3]) : "r"(a));
}

__device__ __forceinline__ void cp16(void* smem, const void* g)
{
    unsigned sa = (unsigned)__cvta_generic_to_shared(smem);
    asm volatile("cp.async.cg.shared.global [%0], [%1], 16;\n"
                 :: "r"(sa), "l"(g) : "memory");
}

// ---------------------------------------------------------------------------
// Batched fp16 converter over up to 7 matrices (first n_small are 1024-block)
// ---------------------------------------------------------------------------
__global__ __launch_bounds__(256)
void split_hi7_kernel(const float4* __restrict__ i0, const float4* __restrict__ i1,
                      const float4* __restrict__ i2, const float4* __restrict__ i3,
                      const float4* __restrict__ i4, const float4* __restrict__ i5,
                      const float4* __restrict__ i6,
                      uint2* __restrict__ o0, uint2* __restrict__ o1,
                      uint2* __restrict__ o2, uint2* __restrict__ o3,
                      uint2* __restrict__ o4, uint2* __restrict__ o5,
                      uint2* __restrict__ o6,
                      int n_small)
{
    const float4* in; uint2* out;
    switch (blockIdx.y) {
        case 0:  in = i0; out = o0; break;
        case 1:  in = i1; out = o1; break;
        case 2:  in = i2; out = o2; break;
        case 3:  in = i3; out = o3; break;
        case 4:  in = i4; out = o4; break;
        case 5:  in = i5; out = o5; break;
        default: in = i6; out = o6; break;
    }
    int nblk = ((int)blockIdx.y < n_small) ? 1024 : 8192;
    if (blockIdx.x >= (unsigned)nblk) return;
    int i = blockIdx.x * 256 + threadIdx.x;
    float4 f = in[i];
    out[i] = make_uint2(pack_f16(f.x, f.y), pack_f16(f.z, f.w));
}

// ---------------------------------------------------------------------------
// Shared GEMM mainloop: fp16 1-pass, BK=64 elements (32 u32) per stage,
// 2-stage cp.async pipeline, ldmatrix fragments.
// ---------------------------------------------------------------------------
#define KPADG 36
#define HALFG (128*KPADG)     // 4608 u32 per operand tile
#define STAGEG (2*HALFG)      // 9216 u32 per stage
#define GEMM_SMEM (2*STAGEG*4)   // 73728 bytes

__device__ __forceinline__ void gemm_mainloop(
    const unsigned* __restrict__ Xhi,
    const unsigned* __restrict__ Whi,
    int m0, int n0, unsigned* sg, float c[4][4][4])
{
    const int t    = threadIdx.x;
    const int lane = t & 31;
    const int wid  = t >> 5;
    const int wm   = wid >> 2;
    const int wn   = wid & 3;

    const int agrp  = lane >> 3;
    const int l7    = lane & 7;
    const int a_row = l7 + ((agrp & 1) << 3);
    const int a_col = (agrp >> 1) << 2;
    const int b_row = l7 + ((agrp >> 1) << 3);
    const int b_col = (agrp & 1) << 2;

    auto issue = [&](int stage, int kt) {
        unsigned* base = sg + stage * STAGEG;
#pragma unroll
        for (int j = 0; j < 8; ++j) {
            int id   = t + j * 256;          // 0..2047
            int half = id >> 10;             // 0..1
            int rem  = id & 1023;
            int row  = rem >> 3;             // 0..127
            int c8   = (rem & 7) << 2;       // u32 offset 0..28
            const unsigned* src;
            if (half == 0) src = Xhi + (size_t)(m0 + row) * 512 + kt * 32 + c8;
            else           src = Whi + (size_t)(n0 + row) * 512 + kt * 32 + c8;
            cp16(base + half * HALFG + row * KPADG + c8, src);
        }
        asm volatile("cp.async.commit_group;\n" ::: "memory");
    };

    issue(0, 0);

    const int NT = 16;   // K=1024 / 64
    for (int kt = 0; kt < NT; ++kt) {
        if (kt + 1 < NT) {
            issue((kt + 1) & 1, kt + 1);
            asm volatile("cp.async.wait_group 1;\n" ::: "memory");
        } else {
            asm volatile("cp.async.wait_group 0;\n" ::: "memory");
        }
        __syncthreads();

        const unsigned* Ah = sg + (kt & 1) * STAGEG;
        const unsigned* Bh = Ah + HALFG;

#pragma unroll
        for (int ks = 0; ks < 4; ++ks) {
            const int pb = ks * 8;
            unsigned ahi[4][4], bhi[2][4];
#pragma unroll
            for (int mf = 0; mf < 4; ++mf) {
                const int r = (wm * 64 + mf * 16 + a_row) * KPADG + pb + a_col;
                ldsm4(ahi[mf], Ah + r);
            }
#pragma unroll
            for (int np = 0; np < 2; ++np) {
                const int r = (wn * 32 + np * 16 + b_row) * KPADG + pb + b_col;
                ldsm4(bhi[np], Bh + r);
            }
#pragma unroll
            for (int mf = 0; mf < 4; ++mf)
#pragma unroll
                for (int nf = 0; nf < 4; ++nf)
                    mma16816f16(c[mf][nf], ahi[mf], &bhi[nf >> 1][(nf & 1) * 2]);
        }
        __syncthreads();
    }
}

// ---------------------------------------------------------------------------
// Merged Q/K/V projection GEMM: z=0 Q (single fp16 out, scaled),
// z=1 K (single fp16 out), z=2 V (transposed single fp16 out). All 1-pass.
// ---------------------------------------------------------------------------
__global__ __launch_bounds__(256, 2)
void gemm_qkv_kernel(const unsigned* __restrict__ xqh,
                     const unsigned* __restrict__ xkh,
                     const unsigned* __restrict__ xvh,
                     const unsigned* __restrict__ wqh,
                     const unsigned* __restrict__ wkh,
                     const unsigned* __restrict__ wvh,
                     const float* __restrict__ bq, const float* __restrict__ bk,
                     const float* __restrict__ bv,
                     unsigned* __restrict__ qh,
                     unsigned* __restrict__ kh,
                     unsigned* __restrict__ vth)
{
    extern __shared__ unsigned sg[];

    const int z = blockIdx.z;
    const unsigned *Xhi, *Whi;
    const float* bias;
    float scale;
    if (z == 0) { Xhi = xqh; Whi = wqh; bias = bq; scale = SCALE_Q; }
    else if (z == 1) { Xhi = xkh; Whi = wkh; bias = bk; scale = 1.0f; }
    else { Xhi = xvh; Whi = wvh; bias = bv; scale = 1.0f; }

    const int t    = threadIdx.x;
    const int lane = t & 31;
    const int wid  = t >> 5;
    const int wm   = wid >> 2;
    const int wn   = wid & 3;
    const int g    = lane >> 2;
    const int tig  = lane & 3;
    const int m0 = blockIdx.y * 128;
    const int n0 = blockIdx.x * 128;

    float c[4][4][4];
#pragma unroll
    for (int i = 0; i < 4; ++i)
#pragma unroll
        for (int j = 0; j < 4; ++j)
#pragma unroll
            for (int e = 0; e < 4; ++e) c[i][j][e] = 0.0f;

    gemm_mainloop(Xhi, Whi, m0, n0, sg, c);

#pragma unroll
    for (int mf = 0; mf < 4; ++mf) {
#pragma unroll
        for (int nf = 0; nf < 4; ++nf) {
            int m = m0 + wm * 64 + mf * 16 + g;
            int n = n0 + wn * 32 + nf * 8 + tig * 2;
            float v0 = (c[mf][nf][0] + bias[n]) * scale;
            float v1 = (c[mf][nf][1] + bias[n + 1]) * scale;
            float v2 = (c[mf][nf][2] + bias[n]) * scale;
            float v3 = (c[mf][nf][3] + bias[n + 1]) * scale;
            int b = m >> 11, s = m & 2047;
            int h = n >> 6, hd = n & 63;
            if (z < 2) {
                unsigned* dst = (z == 0) ? qh : kh;
                size_t p0 = (((size_t)(b * Hc + h)) * Sc + s) * 32 + (hd >> 1);
                size_t p1 = (((size_t)(b * Hc + h)) * Sc + (s + 8)) * 32 + (hd >> 1);
                dst[p0] = pack_f16(v0, v1);
                dst[p1] = pack_f16(v2, v3);
            } else {
                float p0 = __shfl_xor_sync(0xffffffffu, v0, 4);
                float p1 = __shfl_xor_sync(0xffffffffu, v1, 4);
                float p2 = __shfl_xor_sync(0xffffffffu, v2, 4);
                float p3 = __shfl_xor_sync(0xffffffffu, v3, 4);
                if (!(g & 1)) {
                    size_t rb = ((size_t)(b * Hc + h)) * 64;
                    int kp = s >> 1;
                    vth[(rb + hd) * 1024 + kp]         = pack_f16(v0, p0);
                    vth[(rb + hd + 1) * 1024 + kp]     = pack_f16(v1, p1);
                    vth[(rb + hd) * 1024 + kp + 4]     = pack_f16(v2, p2);
                    vth[(rb + hd + 1) * 1024 + kp + 4] = pack_f16(v3, p3);
                }
            }
        }
    }
}

// ---------------------------------------------------------------------------
// Output GEMM: ctx(single fp16) @ Wo(hi)^T + bo -> fp32 out (1-pass)
// ---------------------------------------------------------------------------
__global__ __launch_bounds__(256, 2)
void gemm_out_kernel(const unsigned* __restrict__ Xhi,
                     const unsigned* __restrict__ Whi,
                     const float* __restrict__ bias, float* __restrict__ outf)
{
    extern __shared__ unsigned sg[];

    const int t    = threadIdx.x;
    const int lane = t & 31;
    const int wid  = t >> 5;
    const int wm   = wid >> 2;
    const int wn   = wid & 3;
    const int g    = lane >> 2;
    const int tig  = lane & 3;
    const int m0 = blockIdx.y * 128;
    const int n0 = blockIdx.x * 128;

    float c[4][4][4];
#pragma unroll
    for (int i = 0; i < 4; ++i)
#pragma unroll
        for (int j = 0; j < 4; ++j)
#pragma unroll
            for (int e = 0; e < 4; ++e) c[i][j][e] = 0.0f;

    gemm_mainloop(Xhi, Whi, m0, n0, sg, c);

#pragma unroll
    for (int mf = 0; mf < 4; ++mf) {
#pragma unroll
        for (int nf = 0; nf < 4; ++nf) {
            int m = m0 + wm * 64 + mf * 16 + g;
            int n = n0 + wn * 32 + nf * 8 + tig * 2;
            outf[(size_t)m * Dc + n]           = c[mf][nf][0] + bias[n];
            outf[(size_t)m * Dc + n + 1]       = c[mf][nf][1] + bias[n + 1];
            outf[(size_t)(m + 8) * Dc + n]     = c[mf][nf][2] + bias[n];
            outf[(size_t)(m + 8) * Dc + n + 1] = c[mf][nf][3] + bias[n + 1];
        }
    }
}

// ---------------------------------------------------------------------------
// Flash attention: fp16 1-pass QK, ex2.f16x2 softmax, fp16 P, single-fp16 V
// 1-pass PV, cp.async double-buffered (Kh,Vh per stage).
// ---------------------------------------------------------------------------
#define AT_STAGE_U32 (2*64*36)
#define ATTN6_SMEM_U32 (128*36 + 2*AT_STAGE_U32)
#define ATTN6_SMEM_BYTES (ATTN6_SMEM_U32 * 4)   // 55296

__global__ __launch_bounds__(256, 2)
void attn_mma_kernel(const unsigned* __restrict__ Qhg,
                     const unsigned* __restrict__ Khg,
                     const unsigned* __restrict__ Vthg,
                     unsigned* __restrict__ Chi)
{
    extern __shared__ unsigned smu[];
    unsigned* Qsh = smu;                    // [128][36]
    unsigned* stages = Qsh + 128 * 36;

    const int bh = blockIdx.y;
    const int qt = (int)(gridDim.x - 1 - blockIdx.x);
    const int q0 = qt * 128;
    const int t    = threadIdx.x;
    const int lane = t & 31;
    const int w    = t >> 5;
    const int g    = lane >> 2;
    const int tig  = lane & 3;

    const int agrp  = lane >> 3;
    const int l7    = lane & 7;
    const int a_row = l7 + ((agrp & 1) << 3);
    const int a_col = (agrp >> 1) << 2;
    const int b_row = l7 + ((agrp >> 1) << 3);
    const int b_col = (agrp & 1) << 2;

    const unsigned* Qbh = Qhg + (size_t)bh * Sc * 32;
    const unsigned* Kbh = Khg + (size_t)bh * Sc * 32;
    const unsigned* Vbh = Vthg + (size_t)bh * 64 * 1024;

#pragma unroll
    for (int j = 0; j < 4; ++j) {
        int id = t + j * 256;
        int r = id >> 3, c4 = (id & 7) << 2;
        cp16(&Qsh[r * 36 + c4], &Qbh[(size_t)(q0 + r) * 32 + c4]);
    }
    asm volatile("cp.async.commit_group;\n" ::: "memory");

    auto stage_fn = [&](int st, int kt) {
        unsigned* Kh = stages + st * AT_STAGE_U32;
        unsigned* Vh = Kh + 64 * 36;
        const int k0 = kt * 64, kp0 = kt * 32;
#pragma unroll
        for (int j = 0; j < 2; ++j) {
            int id = t + j * 256;
            int r = id >> 3, c4 = (id & 7) << 2;
            cp16(Kh + r * 36 + c4, Kbh + (size_t)(k0 + r) * 32 + c4);
            cp16(Vh + r * 36 + c4, Vbh + (size_t)r * 1024 + kp0 + c4);
        }
        asm volatile("cp.async.commit_group;\n" ::: "memory");
    };

    float m_i[2] = {-1e30f, -1e30f};
    float l_i[2] = {0.0f, 0.0f};
    float o[8][4];
#pragma unroll
    for (int f = 0; f < 8; ++f)
#pragma unroll
        for (int e = 0; e < 4; ++e) o[f][e] = 0.0f;

    const int row0 = q0 + w * 16 + g;
    const int nkt = 2 * qt + 2;

    stage_fn(0, 0);

    for (int kt = 0; kt < nkt; ++kt) {
        const int k0 = kt * 64;
        __syncthreads();
        if (kt + 1 < nkt) {
            stage_fn((kt + 1) & 1, kt + 1);
            asm volatile("cp.async.wait_group 1;\n" ::: "memory");
        } else {
            asm volatile("cp.async.wait_group 0;\n" ::: "memory");
        }
        __syncthreads();

        if (q0 + w * 16 + 15 < k0) continue;

        const unsigned* Ksh = stages + (kt & 1) * AT_STAGE_U32;
        const unsigned* Vsh = Ksh + 64 * 36;

        // ---- S = Q K^T (fp16 1-pass) ----
        float s[8][4];
#pragma unroll
        for (int nf = 0; nf < 8; ++nf)
#pragma unroll
            for (int e = 0; e < 4; ++e) s[nf][e] = 0.0f;

#pragma unroll
        for (int ks = 0; ks < 4; ++ks) {
            unsigned aq[4];
            const int qoff = (w * 16 + a_row) * 36 + 8 * ks + a_col;
            ldsm4(aq, Qsh + qoff);
            unsigned khi[4][4];
#pragma unroll
            for (int np = 0; np < 4; ++np) {
                const int koff = (np * 16 + b_row) * 36 + 8 * ks + b_col;
                ldsm4(khi[np], Ksh + koff);
            }
#pragma unroll
            for (int nf = 0; nf < 8; ++nf)
                mma16816f16(s[nf], aq, &khi[nf >> 1][(nf & 1) * 2]);
        }

        // ---- causal mask ----
        if (k0 + 63 > q0 + w * 16) {
#pragma unroll
            for (int nf = 0; nf < 8; ++nf) {
                int key = k0 + 8 * nf + 2 * tig;
                if (key     > row0)     s[nf][0] = -1e30f;
                if (key + 1 > row0)     s[nf][1] = -1e30f;
                if (key     > row0 + 8) s[nf][2] = -1e30f;
                if (key + 1 > row0 + 8) s[nf][3] = -1e30f;
            }
        }

        // ---- online softmax (base-2 domain, fp16x2 ex2) ----
        float mx0 = -1e30f, mx1 = -1e30f;
#pragma unroll
        for (int nf = 0; nf < 8; ++nf) {
            mx0 = fmaxf(mx0, fmaxf(s[nf][0], s[nf][1]));
            mx1 = fmaxf(mx1, fmaxf(s[nf][2], s[nf][3]));
        }
        mx0 = fmaxf(mx0, __shfl_xor_sync(0xffffffffu, mx0, 1));
        mx0 = fmaxf(mx0, __shfl_xor_sync(0xffffffffu, mx0, 2));
        mx1 = fmaxf(mx1, __shfl_xor_sync(0xffffffffu, mx1, 1));
        mx1 = fmaxf(mx1, __shfl_xor_sync(0xffffffffu, mx1, 2));

        float mn0 = fmaxf(m_i[0], mx0);
        float mn1 = fmaxf(m_i[1], mx1);
        float cs0 = exp2f(m_i[0] - mn0);
        float cs1 = exp2f(m_i[1] - mn1);
        m_i[0] = mn0; m_i[1] = mn1;

        // P directly in fp16 via ex2.approx.f16x2; l sums the same P used in PV
        unsigned pf[8][2];
        float sum0 = 0.0f, sum1 = 0.0f;
#pragma unroll
        for (int nf = 0; nf < 8; ++nf) {
            pf[nf][0] = ex2_f16x2(s[nf][0] - mn0, s[nf][1] - mn0);
            pf[nf][1] = ex2_f16x2(s[nf][2] - mn1, s[nf][3] - mn1);
            float2 f01 = __half22float2(*reinterpret_cast<__half2*>(&pf[nf][0]));
            float2 f23 = __half22float2(*reinterpret_cast<__half2*>(&pf[nf][1]));
            sum0 += f01.x + f01.y;
            sum1 += f23.x + f23.y;
        }
        sum0 += __shfl_xor_sync(0xffffffffu, sum0, 1);
        sum0 += __shfl_xor_sync(0xffffffffu, sum0, 2);
        sum1 += __shfl_xor_sync(0xffffffffu, sum1, 1);
        sum1 += __shfl_xor_sync(0xffffffffu, sum1, 2);
        l_i[0] = l_i[0] * cs0 + sum0;
        l_i[1] = l_i[1] * cs1 + sum1;

#pragma unroll
        for (int f = 0; f < 8; ++f) {
            o[f][0] *= cs0; o[f][1] *= cs0;
            o[f][2] *= cs1; o[f][3] *= cs1;
        }

        // ---- O += P V (fp16, 1-pass) ----
#pragma unroll
        for (int ks = 0; ks < 4; ++ks) {
            unsigned pa[4] = { pf[2 * ks][0], pf[2 * ks][1],
                               pf[2 * ks + 1][0], pf[2 * ks + 1][1] };
            unsigned vhi[4][4];
#pragma unroll
            for (int np = 0; np < 4; ++np) {
                const int voff = (np * 16 + b_row) * 36 + 8 * ks + b_col;
                ldsm4(vhi[np], Vsh + voff);
            }
#pragma unroll
            for (int nf = 0; nf < 8; ++nf)
                mma16816f16(o[nf], pa, &vhi[nf >> 1][(nf & 1) * 2]);
        }
    }

    // ---- epilogue: normalize, single fp16, write ctx ----
    const float inv0 = 1.0f / l_i[0];
    const float inv1 = 1.0f / l_i[1];
    const int b = bh >> 4;
    const int h = bh & 15;
#pragma unroll
    for (int nf = 0; nf < 8; ++nf) {
        int col = 8 * nf + 2 * tig;
        size_t p0 = ((size_t)b * Sc + row0) * 512 + h * 32 + (col >> 1);
        size_t p1 = ((size_t)b * Sc + row0 + 8) * 512 + h * 32 + (col >> 1);
        Chi[p0] = pack_f16(o[nf][0] * inv0, o[nf][1] * inv0);
        Chi[p1] = pack_f16(o[nf][2] * inv1, o[nf][3] * inv1);
    }
}

// ---------------------------------------------------------------------------
// Launch
// ---------------------------------------------------------------------------
#define SYMADDR(p, s) do { void* _tmp; cudaGetSymbolAddress(&_tmp, s); p = (unsigned*)_tmp; } while (0)

extern "C" void kernel_launch(void* const* d_in, const int* in_sizes, int n_in,
                              void* d_out, int out_size)
{
    const float* q  = (const float*)d_in[0];
    const float* k  = (const float*)d_in[1];
    const float* v  = (const float*)d_in[2];
    const float* Wq = (const float*)d_in[4];
    const float* bq = (const float*)d_in[5];
    const float* Wk = (const float*)d_in[6];
    const float* bk = (const float*)d_in[7];
    const float* Wv = (const float*)d_in[8];
    const float* bv = (const float*)d_in[9];
    const float* Wo = (const float*)d_in[10];
    const float* bo = (const float*)d_in[11];
    float* out = (float*)d_out;

    unsigned *wqh,*wkh,*wvh,*woh;
    unsigned *xqh,*xkh,*xvh;
    unsigned *qh,*kh,*vth,*ch;
    SYMADDR(wqh, g_Wqhi); SYMADDR(wkh, g_Wkhi);
    SYMADDR(wvh, g_Wvhi); SYMADDR(woh, g_Wohi);
    SYMADDR(xqh, g_Xqhi); SYMADDR(xkh, g_Xkhi); SYMADDR(xvh, g_Xvhi);
    SYMADDR(qh, g_Qhi);   SYMADDR(kh, g_Khi);
    SYMADDR(vth, g_Vthi);
    SYMADDR(ch, g_Chi);

    cudaFuncSetAttribute(gemm_qkv_kernel, cudaFuncAttributeMaxDynamicSharedMemorySize, GEMM_SMEM);
    cudaFuncSetAttribute(gemm_out_kernel, cudaFuncAttributeMaxDynamicSharedMemorySize, GEMM_SMEM);
    cudaFuncSetAttribute(attn_mma_kernel, cudaFuncAttributeMaxDynamicSharedMemorySize, ATTN6_SMEM_BYTES);

    split_hi7_kernel<<<dim3(8192, 7), 256>>>(
        (const float4*)Wq, (const float4*)Wk, (const float4*)Wv, (const float4*)Wo,
        (const float4*)q, (const float4*)k, (const float4*)v,
        (uint2*)wqh, (uint2*)wkh, (uint2*)wvh, (uint2*)woh,
        (uint2*)xqh, (uint2*)xkh, (uint2*)xvh, 4);

    dim3 gg3(Dc / 128, Mrows / 128, 3);   // (8, 64, 3)
    gemm_qkv_kernel<<<gg3, 256, GEMM_SMEM>>>(
        xqh, xkh, xvh,
        wqh, wkh, wvh,
        bq, bk, bv,
        qh, kh, vth);

    dim3 ga(Sc / 128, Bc * Hc);           // (16, 64)
    attn_mma_kernel<<<ga, 256, ATTN6_SMEM_BYTES>>>(qh, kh, vth, ch);

    dim3 gg(Dc / 128, Mrows / 128);       // (8, 64)
    gemm_out_kernel<<<gg, 256, GEMM_SMEM>>>(ch, woh, bo, out);
}